// round 4
// baseline (speedup 1.0000x reference)
#include <cuda_runtime.h>
#include <cstdint>

#define PB 2
#define PS 2048
#define PE 1024
#define PH 16
#define PHD 64
#define MROWS (PB * PS * PH)
#define PAD 68   // 64-col tiles: (r*68 + c) mod 32 = 4r+c -> fragment loads conflict-free
#define PAD2 36  // 32-col tiles: same property

// Scratch, all tf32 bit patterns stored as uint32 (allocation-free rule)
__device__ uint32_t g_Q[(size_t)PB * PH * PS * PHD];
__device__ uint32_t g_K[(size_t)PB * PH * PS * PHD];
__device__ uint32_t g_V[(size_t)PB * PH * PS * PHD];
__device__ uint32_t g_Y[(size_t)PB * PS * PE];
__device__ uint32_t g_Wp[(size_t)PE * PE];
__device__ uint32_t g_Wq[PHD * PHD];
__device__ uint32_t g_Wk[PHD * PHD];
__device__ uint32_t g_Wv[PHD * PHD];

__device__ __forceinline__ uint32_t f2tf(float x) {
  uint32_t u;
  asm("cvt.rna.tf32.f32 %0, %1;" : "=r"(u) : "f"(x));
  return u;
}
__device__ __forceinline__ float ex2(float x) {
  float y;
  asm("ex2.approx.ftz.f32 %0, %1;" : "=f"(y) : "f"(x));
  return y;
}
__device__ __forceinline__ void mma_tf32(float c[4], uint32_t a0, uint32_t a1,
                                         uint32_t a2, uint32_t a3, uint32_t b0,
                                         uint32_t b1) {
  asm volatile(
      "mma.sync.aligned.m16n8k8.row.col.f32.tf32.tf32.f32 "
      "{%0,%1,%2,%3}, {%4,%5,%6,%7}, {%8,%9}, {%0,%1,%2,%3};"
      : "+f"(c[0]), "+f"(c[1]), "+f"(c[2]), "+f"(c[3])
      : "r"(a0), "r"(a1), "r"(a2), "r"(a3), "r"(b0), "r"(b1));
}
__device__ __forceinline__ void cpa16(uint32_t* smem_dst, const void* gsrc) {
  uint32_t d = (uint32_t)__cvta_generic_to_shared(smem_dst);
  asm volatile("cp.async.cg.shared.global [%0], [%1], 16;" ::"r"(d), "l"(gsrc));
}
__device__ __forceinline__ void cp_commit() {
  asm volatile("cp.async.commit_group;");
}
__device__ __forceinline__ void cp_wait1() {
  asm volatile("cp.async.wait_group 1;");
}
__device__ __forceinline__ void cp_wait0() {
  asm volatile("cp.async.wait_group 0;");
}

// ---------------------------------------------------------------------------
// Kernel 0: one-time tf32 pre-conversion of weights.
// ---------------------------------------------------------------------------
__global__ __launch_bounds__(256) void prep_kernel(
    const float* __restrict__ Wp, const float* __restrict__ Wq,
    const float* __restrict__ Wk, const float* __restrict__ Wv) {
  int i = blockIdx.x * 256 + threadIdx.x;
  if (i < PE * PE) g_Wp[i] = f2tf(Wp[i]);
  if (i < PHD * PHD) {
    g_Wq[i] = f2tf(Wq[i]);
    g_Wk[i] = f2tf(Wk[i]);
    g_Wv[i] = f2tf(Wv[i]);
  }
}

// ---------------------------------------------------------------------------
// Kernel 1: fused QKV projection. 512 thr, 128 rows/block.
// Q output pre-scaled by (1/sqrt(64))*log2(e) so attention uses ex2 directly.
// ---------------------------------------------------------------------------
__global__ __launch_bounds__(512) void qkv_kernel(
    const float* __restrict__ x, const float* __restrict__ bq,
    const float* __restrict__ bk, const float* __restrict__ bv) {
  extern __shared__ uint32_t sm[];
  uint32_t* Xs = sm;               // 128*PAD
  uint32_t* Aq = Xs + 128 * PAD;   // 64*PAD each
  uint32_t* Ak = Aq + 64 * PAD;
  uint32_t* Av = Ak + 64 * PAD;
  const int tid = threadIdx.x;
  const int rowbase = blockIdx.x * 128;

#pragma unroll
  for (int r = 0; r < 2; r++) {
    int f = tid + 512 * r;
    int row = f >> 4, col = (f & 15) * 4;
    cpa16(&Aq[row * PAD + col], &g_Wq[row * 64 + col]);
    cpa16(&Ak[row * PAD + col], &g_Wk[row * 64 + col]);
    cpa16(&Av[row * PAD + col], &g_Wv[row * 64 + col]);
  }
  cp_commit();
#pragma unroll
  for (int r = 0; r < 4; r++) {
    int f = tid + 512 * r;
    int row = f >> 4, col = (f & 15) * 4;
    float4 v = *(const float4*)&x[(size_t)(rowbase + row) * 64 + col];
    uint4 u = {f2tf(v.x), f2tf(v.y), f2tf(v.z), f2tf(v.w)};
    *(uint4*)&Xs[row * PAD + col] = u;
  }
  cp_wait0();
  __syncthreads();

  const int wid = tid >> 5, lane = tid & 31;
  const int g = lane >> 2, t = lane & 3;
  const int mrow = (wid & 7) * 16;
  const int wn = wid >> 3;

  float cq[4][4] = {}, ck[4][4] = {}, cv[4][4] = {};
#pragma unroll
  for (int k0 = 0; k0 < 64; k0 += 8) {
    uint32_t a0 = Xs[(mrow + g) * PAD + k0 + t];
    uint32_t a1 = Xs[(mrow + g + 8) * PAD + k0 + t];
    uint32_t a2 = Xs[(mrow + g) * PAD + k0 + t + 4];
    uint32_t a3 = Xs[(mrow + g + 8) * PAD + k0 + t + 4];
#pragma unroll
    for (int nt = 0; nt < 4; nt++) {
      int n0 = wn * 32 + nt * 8;
      mma_tf32(cq[nt], a0, a1, a2, a3, Aq[(n0 + g) * PAD + k0 + t],
               Aq[(n0 + g) * PAD + k0 + t + 4]);
      mma_tf32(ck[nt], a0, a1, a2, a3, Ak[(n0 + g) * PAD + k0 + t],
               Ak[(n0 + g) * PAD + k0 + t + 4]);
      mma_tf32(cv[nt], a0, a1, a2, a3, Av[(n0 + g) * PAD + k0 + t],
               Av[(n0 + g) * PAD + k0 + t + 4]);
    }
  }

  const float qscale = 0.125f * 1.4426950408889634f;  // 1/sqrt(64) * log2(e)
#pragma unroll
  for (int nt = 0; nt < 4; nt++)
#pragma unroll
    for (int i = 0; i < 4; i++) {
      int row = rowbase + mrow + g + ((i >= 2) ? 8 : 0);
      int col = wn * 32 + nt * 8 + 2 * t + (i & 1);
      int b = row >> 15;              // row / (S*H)
      int s = (row >> 4) & (PS - 1);  // (row / H) % S
      int h = row & 15;
      size_t base = ((size_t)(b * PH + h) * PS + s) * PHD + col;
      g_Q[base] = f2tf((cq[nt][i] + bq[col]) * qscale);
      g_K[base] = f2tf(ck[nt][i] + bk[col]);
      g_V[base] = f2tf(cv[nt][i] + bv[col]);
    }
}

// ---------------------------------------------------------------------------
// Kernel 2: causal flash attention. 256 thr, 128 queries/block.
// 32-row KV stages in a 3-slot cp.async ring; ONE __syncthreads per stage.
// ---------------------------------------------------------------------------
__global__ __launch_bounds__(256) void attn_kernel() {
  extern __shared__ uint32_t sm[];
  uint32_t* Qs = sm;                     // 128*PAD
  uint32_t* Ks = Qs + 128 * PAD;         // 3 slots x 32*PAD
  uint32_t* Vs = Ks + 3 * 32 * PAD;      // 3 slots x 32*PAD
  uint32_t* Ps = Vs + 3 * 32 * PAD;      // 128*PAD2
  const int tid = threadIdx.x;
  const int wid = tid >> 5, lane = tid & 31;
  const int g = lane >> 2, t = lane & 3;
  const int mrow = wid * 16;
  const int bh = blockIdx.y;
  const int qi = (PS / 128 - 1) - blockIdx.x;  // big tiles first
  const int ntiles = 4 * qi + 4;

  const uint32_t* Qg = g_Q + ((size_t)bh * PS + (size_t)qi * 128) * PHD;
  const uint32_t* Kg = g_K + (size_t)bh * PS * PHD;
  const uint32_t* Vg = g_V + (size_t)bh * PS * PHD;

  const int crow = tid >> 4, ccol = (tid & 15) * 4;  // 256-thr copy shape

  // Prologue: group0 = Q + KV stage0, group1 = KV stage1
#pragma unroll
  for (int r = 0; r < 8; r++) {
    int f = tid + 256 * r;
    int row = f >> 4, col = (f & 15) * 4;
    cpa16(&Qs[row * PAD + col], &Qg[row * 64 + col]);
  }
  {
    cpa16(&Ks[crow * PAD + ccol], &Kg[crow * 64 + ccol]);
    cpa16(&Ks[(crow + 16) * PAD + ccol], &Kg[(crow + 16) * 64 + ccol]);
    cpa16(&Vs[crow * PAD + ccol], &Vg[crow * 64 + ccol]);
    cpa16(&Vs[(crow + 16) * PAD + ccol], &Vg[(crow + 16) * 64 + ccol]);
  }
  cp_commit();
  if (ntiles > 1) {
    const uint32_t* Kn = Kg + 32 * 64;
    const uint32_t* Vn = Vg + 32 * 64;
    cpa16(&Ks[(32 + crow) * PAD + ccol], &Kn[crow * 64 + ccol]);
    cpa16(&Ks[(32 + crow + 16) * PAD + ccol], &Kn[(crow + 16) * 64 + ccol]);
    cpa16(&Vs[(32 + crow) * PAD + ccol], &Vn[crow * 64 + ccol]);
    cpa16(&Vs[(32 + crow + 16) * PAD + ccol], &Vn[(crow + 16) * 64 + ccol]);
  }
  cp_commit();

  float m0 = -1e30f, m1 = -1e30f, l0 = 0.f, l1 = 0.f;
  float o[8][4] = {};
  const int qrow0 = qi * 128 + mrow + g;

  for (int j = 0; j < ntiles; j++) {
    cp_wait1();       // group for stage j complete (groups j+1 may be pending)
    __syncthreads();  // stage j visible; all warps done with slot (j-1)%3

    // Prefetch stage j+2 into slot (j+2)%3 == slot last used at iter j-1
    if (j + 2 < ntiles) {
      const int sl = (j + 2) % 3;
      const uint32_t* Kn = Kg + (size_t)(j + 2) * 32 * 64;
      const uint32_t* Vn = Vg + (size_t)(j + 2) * 32 * 64;
      cpa16(&Ks[(sl * 32 + crow) * PAD + ccol], &Kn[crow * 64 + ccol]);
      cpa16(&Ks[(sl * 32 + crow + 16) * PAD + ccol], &Kn[(crow + 16) * 64 + ccol]);
      cpa16(&Vs[(sl * 32 + crow) * PAD + ccol], &Vn[crow * 64 + ccol]);
      cpa16(&Vs[(sl * 32 + crow + 16) * PAD + ccol], &Vn[(crow + 16) * 64 + ccol]);
    }
    cp_commit();  // commit every iter (possibly empty) to keep group count aligned

    const uint32_t* Kb = Ks + (j % 3) * 32 * PAD;
    const uint32_t* Vb = Vs + (j % 3) * 32 * PAD;

    // S = Q @ K^T  (128 x 32 chunk)
    float s[4][4] = {};
#pragma unroll
    for (int k0 = 0; k0 < 64; k0 += 8) {
      uint32_t a0 = Qs[(mrow + g) * PAD + k0 + t];
      uint32_t a1 = Qs[(mrow + g + 8) * PAD + k0 + t];
      uint32_t a2 = Qs[(mrow + g) * PAD + k0 + t + 4];
      uint32_t a3 = Qs[(mrow + g + 8) * PAD + k0 + t + 4];
#pragma unroll
      for (int nt = 0; nt < 4; nt++) {
        mma_tf32(s[nt], a0, a1, a2, a3, Kb[(nt * 8 + g) * PAD + k0 + t],
                 Kb[(nt * 8 + g) * PAD + k0 + t + 4]);
      }
    }

    if (j >= 4 * qi) {  // only the 4 diagonal-band tiles can clip
#pragma unroll
      for (int nt = 0; nt < 4; nt++)
#pragma unroll
        for (int i = 0; i < 4; i++) {
          int col = j * 32 + nt * 8 + 2 * t + (i & 1);
          int row = qrow0 + ((i >= 2) ? 8 : 0);
          if (col > row) s[nt][i] = -1e30f;
        }
    }

    // online softmax (log2 domain), rows warp-local, quad reduce
    float rmax0 = -1e30f, rmax1 = -1e30f;
#pragma unroll
    for (int nt = 0; nt < 4; nt++) {
      rmax0 = fmaxf(rmax0, fmaxf(s[nt][0], s[nt][1]));
      rmax1 = fmaxf(rmax1, fmaxf(s[nt][2], s[nt][3]));
    }
    rmax0 = fmaxf(rmax0, __shfl_xor_sync(0xffffffffu, rmax0, 1));
    rmax0 = fmaxf(rmax0, __shfl_xor_sync(0xffffffffu, rmax0, 2));
    rmax1 = fmaxf(rmax1, __shfl_xor_sync(0xffffffffu, rmax1, 1));
    rmax1 = fmaxf(rmax1, __shfl_xor_sync(0xffffffffu, rmax1, 2));

    float nm0 = fmaxf(m0, rmax0), nm1 = fmaxf(m1, rmax1);
    float sc0 = ex2(m0 - nm0), sc1 = ex2(m1 - nm1);
    m0 = nm0;
    m1 = nm1;

    float rs0 = 0.f, rs1 = 0.f;
#pragma unroll
    for (int nt = 0; nt < 4; nt++)
#pragma unroll
      for (int i = 0; i < 4; i++) {
        float nm = (i >= 2) ? nm1 : nm0;
        uint32_t u = f2tf(ex2(s[nt][i] - nm));
        float pf = __uint_as_float(u);  // l matches tf32-rounded P exactly
        if (i >= 2) rs1 += pf; else rs0 += pf;
        Ps[(mrow + g + ((i >= 2) ? 8 : 0)) * PAD2 + nt * 8 + 2 * t + (i & 1)] = u;
      }
    rs0 += __shfl_xor_sync(0xffffffffu, rs0, 1);
    rs0 += __shfl_xor_sync(0xffffffffu, rs0, 2);
    rs1 += __shfl_xor_sync(0xffffffffu, rs1, 1);
    rs1 += __shfl_xor_sync(0xffffffffu, rs1, 2);
    l0 = l0 * sc0 + rs0;
    l1 = l1 * sc1 + rs1;
#pragma unroll
    for (int nt = 0; nt < 8; nt++) {
      o[nt][0] *= sc0;
      o[nt][1] *= sc0;
      o[nt][2] *= sc1;
      o[nt][3] *= sc1;
    }

    __syncwarp();  // Ps rows are warp-private; order STS before LDS

    // O += P @ V  (128x32 @ 32x64)
#pragma unroll
    for (int k0 = 0; k0 < 32; k0 += 8) {
      uint32_t a0 = Ps[(mrow + g) * PAD2 + k0 + t];
      uint32_t a1 = Ps[(mrow + g + 8) * PAD2 + k0 + t];
      uint32_t a2 = Ps[(mrow + g) * PAD2 + k0 + t + 4];
      uint32_t a3 = Ps[(mrow + g + 8) * PAD2 + k0 + t + 4];
#pragma unroll
      for (int nt = 0; nt < 8; nt++) {
        mma_tf32(o[nt], a0, a1, a2, a3, Vb[(k0 + t) * PAD + nt * 8 + g],
                 Vb[(k0 + t + 4) * PAD + nt * 8 + g]);
      }
    }
  }

  const int b = bh >> 4, h = bh & 15;
  float inv0 = 1.f / l0, inv1 = 1.f / l1;
#pragma unroll
  for (int nt = 0; nt < 8; nt++)
#pragma unroll
    for (int i = 0; i < 4; i++) {
      int srow = qi * 128 + mrow + g + ((i >= 2) ? 8 : 0);
      int col = nt * 8 + 2 * t + (i & 1);
      g_Y[((size_t)b * PS + srow) * PE + h * PHD + col] =
          f2tf(o[nt][i] * ((i >= 2) ? inv1 : inv0));
    }
}

// ---------------------------------------------------------------------------
// Kernel 3: output projection. 512 thr, 128x256 tile/block (grid = 128 blocks
// = one wave on 148 SMs). 32-deep K stages, 3-slot cp.async ring, one barrier
// per stage.
// ---------------------------------------------------------------------------
__global__ __launch_bounds__(512) void proj_kernel(
    const float* __restrict__ bias, float* __restrict__ out) {
  extern __shared__ uint32_t sm[];
  // Per stage: Y 128*PAD2 then W 256*PAD2  (stage stride SSTR)
  const int SSTR = (128 + 256) * PAD2;
  uint32_t* Ys = sm;
  uint32_t* Ws = sm + 128 * PAD2;
  const int tid = threadIdx.x;
  const int wid = tid >> 5, lane = tid & 31;
  const int g = lane >> 2, t = lane & 3;
  const int mrow = (wid & 7) * 16;
  const int wn = wid >> 3;  // 0..1, 128 cols each
  const int bm = blockIdx.y, bn = blockIdx.x;

  const uint32_t* Yg = g_Y + (size_t)bm * 128 * PE;
  const uint32_t* Wg = g_Wp + (size_t)bn * 256 * PE;

  const int yrow = tid >> 3, ycol = (tid & 7) * 4;   // 512 thr: 64 rows/pass
  const int NK = PE / 32;

  // Prologue: stages 0 and 1
#pragma unroll
  for (int st = 0; st < 2; st++) {
#pragma unroll
    for (int r = 0; r < 2; r++)
      cpa16(&Ys[st * SSTR + (yrow + 64 * r) * PAD2 + ycol],
            &Yg[(size_t)(yrow + 64 * r) * PE + st * 32 + ycol]);
#pragma unroll
    for (int r = 0; r < 4; r++)
      cpa16(&Ws[st * SSTR + (yrow + 64 * r) * PAD2 + ycol],
            &Wg[(size_t)(yrow + 64 * r) * PE + st * 32 + ycol]);
    cp_commit();
  }

  float acc[16][4] = {};
  for (int kt = 0; kt < NK; kt++) {
    cp_wait1();
    __syncthreads();

    if (kt + 2 < NK) {
      const int sl = (kt + 2) % 3;
#pragma unroll
      for (int r = 0; r < 2; r++)
        cpa16(&Ys[sl * SSTR + (yrow + 64 * r) * PAD2 + ycol],
              &Yg[(size_t)(yrow + 64 * r) * PE + (kt + 2) * 32 + ycol]);
#pragma unroll
      for (int r = 0; r < 4; r++)
        cpa16(&Ws[sl * SSTR + (yrow + 64 * r) * PAD2 + ycol],
              &Wg[(size_t)(yrow + 64 * r) * PE + (kt + 2) * 32 + ycol]);
    }
    cp_commit();

    const uint32_t* Yb = Ys + (kt % 3) * SSTR;
    const uint32_t* Wb = Ws + (kt % 3) * SSTR;
#pragma unroll
    for (int k0 = 0; k0 < 32; k0 += 8) {
      uint32_t a0 = Yb[(mrow + g) * PAD2 + k0 + t];
      uint32_t a1 = Yb[(mrow + g + 8) * PAD2 + k0 + t];
      uint32_t a2 = Yb[(mrow + g) * PAD2 + k0 + t + 4];
      uint32_t a3 = Yb[(mrow + g + 8) * PAD2 + k0 + t + 4];
#pragma unroll
      for (int nt = 0; nt < 16; nt++) {
        int n0 = wn * 128 + nt * 8;
        mma_tf32(acc[nt], a0, a1, a2, a3, Wb[(n0 + g) * PAD2 + k0 + t],
                 Wb[(n0 + g) * PAD2 + k0 + t + 4]);
      }
    }
  }

#pragma unroll
  for (int nt = 0; nt < 16; nt++)
#pragma unroll
    for (int i = 0; i < 4; i++) {
      int row = bm * 128 + mrow + g + ((i >= 2) ? 8 : 0);
      int col = bn * 256 + wn * 128 + nt * 8 + 2 * t + (i & 1);
      out[(size_t)row * PE + col] = acc[nt][i] + bias[col];
    }
}

// ---------------------------------------------------------------------------
extern "C" void kernel_launch(void* const* d_in, const int* in_sizes, int n_in,
                              void* d_out, int out_size) {
  const float* x  = (const float*)d_in[0];
  const float* Wq = (const float*)d_in[1];
  const float* bq = (const float*)d_in[2];
  const float* Wk = (const float*)d_in[3];
  const float* bk = (const float*)d_in[4];
  const float* Wv = (const float*)d_in[5];
  const float* bv = (const float*)d_in[6];
  const float* Wp = (const float*)d_in[7];
  const float* bp = (const float*)d_in[8];
  float* out = (float*)d_out;

  const int smem_qkv  = (128 + 3 * 64) * PAD * 4;                     // 87,040 B
  const int smem_attn = (128 * PAD + 6 * 32 * PAD + 128 * PAD2) * 4;  // 105,472 B
  const int smem_proj = 3 * (128 + 256) * PAD2 * 4;                   // 165,888 B
  cudaFuncSetAttribute(qkv_kernel, cudaFuncAttributeMaxDynamicSharedMemorySize, smem_qkv);
  cudaFuncSetAttribute(attn_kernel, cudaFuncAttributeMaxDynamicSharedMemorySize, smem_attn);
  cudaFuncSetAttribute(proj_kernel, cudaFuncAttributeMaxDynamicSharedMemorySize, smem_proj);

  prep_kernel<<<(PE * PE + 255) / 256, 256>>>(Wp, Wq, Wk, Wv);
  qkv_kernel<<<MROWS / 128, 512, smem_qkv>>>(x, bq, bk, bv);
  attn_kernel<<<dim3(PS / 128, PB * PH), 256, smem_attn>>>();
  proj_kernel<<<dim3(PE / 256, (PB * PS) / 128), 512, smem_proj>>>(bp, out);
}

// round 5
// speedup vs baseline: 1.6092x; 1.6092x over previous
#include <cuda_runtime.h>
#include <cstdint>

#define PB 2
#define PS 2048
#define PE 1024
#define PH 16
#define PHD 64
#define MROWS (PB * PS * PH)
#define PAD 68   // 64-col tiles: (r*68 + c) mod 32 = 4r+c -> fragment loads conflict-free
#define PAD2 36  // 32-col tiles: same property

// Scratch, all tf32 bit patterns stored as uint32 (allocation-free rule)
__device__ uint32_t g_Q[(size_t)PB * PH * PS * PHD];
__device__ uint32_t g_K[(size_t)PB * PH * PS * PHD];
__device__ uint32_t g_V[(size_t)PB * PH * PS * PHD];
__device__ uint32_t g_Y[(size_t)PB * PS * PE];
__device__ uint32_t g_Wp[(size_t)PE * PE];
__device__ uint32_t g_Wq[PHD * PHD];
__device__ uint32_t g_Wk[PHD * PHD];
__device__ uint32_t g_Wv[PHD * PHD];

__device__ __forceinline__ uint32_t f2tf(float x) {
  uint32_t u;
  asm("cvt.rna.tf32.f32 %0, %1;" : "=r"(u) : "f"(x));
  return u;
}
__device__ __forceinline__ float ex2(float x) {
  float y;
  asm("ex2.approx.ftz.f32 %0, %1;" : "=f"(y) : "f"(x));
  return y;
}
__device__ __forceinline__ void mma_tf32(float c[4], uint32_t a0, uint32_t a1,
                                         uint32_t a2, uint32_t a3, uint32_t b0,
                                         uint32_t b1) {
  asm volatile(
      "mma.sync.aligned.m16n8k8.row.col.f32.tf32.tf32.f32 "
      "{%0,%1,%2,%3}, {%4,%5,%6,%7}, {%8,%9}, {%0,%1,%2,%3};"
      : "+f"(c[0]), "+f"(c[1]), "+f"(c[2]), "+f"(c[3])
      : "r"(a0), "r"(a1), "r"(a2), "r"(a3), "r"(b0), "r"(b1));
}
__device__ __forceinline__ void cpa16(uint32_t* smem_dst, const void* gsrc) {
  uint32_t d = (uint32_t)__cvta_generic_to_shared(smem_dst);
  asm volatile("cp.async.cg.shared.global [%0], [%1], 16;" ::"r"(d), "l"(gsrc));
}
__device__ __forceinline__ void cp_commit() {
  asm volatile("cp.async.commit_group;");
}
__device__ __forceinline__ void cp_wait1() {
  asm volatile("cp.async.wait_group 1;");
}
__device__ __forceinline__ void cp_wait0() {
  asm volatile("cp.async.wait_group 0;");
}

// ---------------------------------------------------------------------------
// Kernel 0: one-time tf32 pre-conversion of weights.
// ---------------------------------------------------------------------------
__global__ __launch_bounds__(256) void prep_kernel(
    const float* __restrict__ Wp, const float* __restrict__ Wq,
    const float* __restrict__ Wk, const float* __restrict__ Wv) {
  int i = blockIdx.x * 256 + threadIdx.x;
  if (i < PE * PE) g_Wp[i] = f2tf(Wp[i]);
  if (i < PHD * PHD) {
    g_Wq[i] = f2tf(Wq[i]);
    g_Wk[i] = f2tf(Wk[i]);
    g_Wv[i] = f2tf(Wv[i]);
  }
}

// ---------------------------------------------------------------------------
// Kernel 1: fused QKV projection. 512 thr, 128 rows/block.
// Q output pre-scaled by (1/sqrt(64))*log2(e) so attention uses ex2 directly.
// ---------------------------------------------------------------------------
__global__ __launch_bounds__(512) void qkv_kernel(
    const float* __restrict__ x, const float* __restrict__ bq,
    const float* __restrict__ bk, const float* __restrict__ bv) {
  extern __shared__ uint32_t sm[];
  uint32_t* Xs = sm;               // 128*PAD
  uint32_t* Aq = Xs + 128 * PAD;   // 64*PAD each
  uint32_t* Ak = Aq + 64 * PAD;
  uint32_t* Av = Ak + 64 * PAD;
  const int tid = threadIdx.x;
  const int rowbase = blockIdx.x * 128;

#pragma unroll
  for (int r = 0; r < 2; r++) {
    int f = tid + 512 * r;
    int row = f >> 4, col = (f & 15) * 4;
    cpa16(&Aq[row * PAD + col], &g_Wq[row * 64 + col]);
    cpa16(&Ak[row * PAD + col], &g_Wk[row * 64 + col]);
    cpa16(&Av[row * PAD + col], &g_Wv[row * 64 + col]);
  }
  cp_commit();
#pragma unroll
  for (int r = 0; r < 4; r++) {
    int f = tid + 512 * r;
    int row = f >> 4, col = (f & 15) * 4;
    float4 v = *(const float4*)&x[(size_t)(rowbase + row) * 64 + col];
    uint4 u = {f2tf(v.x), f2tf(v.y), f2tf(v.z), f2tf(v.w)};
    *(uint4*)&Xs[row * PAD + col] = u;
  }
  cp_wait0();
  __syncthreads();

  const int wid = tid >> 5, lane = tid & 31;
  const int g = lane >> 2, t = lane & 3;
  const int mrow = (wid & 7) * 16;
  const int wn = wid >> 3;

  float cq[4][4] = {}, ck[4][4] = {}, cv[4][4] = {};
#pragma unroll
  for (int k0 = 0; k0 < 64; k0 += 8) {
    uint32_t a0 = Xs[(mrow + g) * PAD + k0 + t];
    uint32_t a1 = Xs[(mrow + g + 8) * PAD + k0 + t];
    uint32_t a2 = Xs[(mrow + g) * PAD + k0 + t + 4];
    uint32_t a3 = Xs[(mrow + g + 8) * PAD + k0 + t + 4];
#pragma unroll
    for (int nt = 0; nt < 4; nt++) {
      int n0 = wn * 32 + nt * 8;
      mma_tf32(cq[nt], a0, a1, a2, a3, Aq[(n0 + g) * PAD + k0 + t],
               Aq[(n0 + g) * PAD + k0 + t + 4]);
      mma_tf32(ck[nt], a0, a1, a2, a3, Ak[(n0 + g) * PAD + k0 + t],
               Ak[(n0 + g) * PAD + k0 + t + 4]);
      mma_tf32(cv[nt], a0, a1, a2, a3, Av[(n0 + g) * PAD + k0 + t],
               Av[(n0 + g) * PAD + k0 + t + 4]);
    }
  }

  const float qscale = 0.125f * 1.4426950408889634f;  // 1/sqrt(64) * log2(e)
#pragma unroll
  for (int nt = 0; nt < 4; nt++)
#pragma unroll
    for (int i = 0; i < 4; i++) {
      int row = rowbase + mrow + g + ((i >= 2) ? 8 : 0);
      int col = wn * 32 + nt * 8 + 2 * t + (i & 1);
      int b = row >> 15;              // row / (S*H)
      int s = (row >> 4) & (PS - 1);  // (row / H) % S
      int h = row & 15;
      size_t base = ((size_t)(b * PH + h) * PS + s) * PHD + col;
      g_Q[base] = f2tf((cq[nt][i] + bq[col]) * qscale);
      g_K[base] = f2tf(ck[nt][i] + bk[col]);
      g_V[base] = f2tf(cv[nt][i] + bv[col]);
    }
}

// ---------------------------------------------------------------------------
// Kernel 2: causal flash attention, 256 thr, 128 queries/block, 32-row KV
// stages double-buffered with cp.async (R3 structure). Q fragments hoisted
// into registers for the whole KV loop.
// ---------------------------------------------------------------------------
__global__ __launch_bounds__(256) void attn_kernel() {
  extern __shared__ uint32_t sm[];
  uint32_t* Qs = sm;                     // 128*PAD
  uint32_t* Ks = Qs + 128 * PAD;         // 2 bufs x 32*PAD
  uint32_t* Vs = Ks + 2 * 32 * PAD;      // 2 bufs x 32*PAD
  uint32_t* Ps = Vs + 2 * 32 * PAD;      // 128*PAD2
  const int tid = threadIdx.x;
  const int wid = tid >> 5, lane = tid & 31;
  const int g = lane >> 2, t = lane & 3;
  const int mrow = wid * 16;
  const int bh = blockIdx.y;
  const int qi = (PS / 128 - 1) - blockIdx.x;  // big tiles first
  const int ntiles = 4 * qi + 4;

  const uint32_t* Qg = g_Q + ((size_t)bh * PS + (size_t)qi * 128) * PHD;
  const uint32_t* Kg = g_K + (size_t)bh * PS * PHD;
  const uint32_t* Vg = g_V + (size_t)bh * PS * PHD;

  // Prologue group: Q tile + KV stage 0
#pragma unroll
  for (int r = 0; r < 8; r++) {
    int f = tid + 256 * r;
    int row = f >> 4, col = (f & 15) * 4;
    cpa16(&Qs[row * PAD + col], &Qg[row * 64 + col]);
  }
#pragma unroll
  for (int r = 0; r < 2; r++) {
    int f = tid + 256 * r;
    int row = f >> 4, col = (f & 15) * 4;
    cpa16(&Ks[row * PAD + col], &Kg[row * 64 + col]);
    cpa16(&Vs[row * PAD + col], &Vg[row * 64 + col]);
  }
  cp_commit();

  float m0 = -1e30f, m1 = -1e30f, l0 = 0.f, l1 = 0.f;
  float o[8][4] = {};
  uint32_t qf[8][4];  // Q fragments, filled at j==0, live for the whole loop
  const int qrow0 = qi * 128 + mrow + g;

  for (int j = 0; j < ntiles; j++) {
    const int buf = j & 1;
    if (j + 1 < ntiles) {
      const int nb = (j + 1) & 1;
      const uint32_t* Kn = Kg + (size_t)(j + 1) * 32 * 64;
      const uint32_t* Vn = Vg + (size_t)(j + 1) * 32 * 64;
#pragma unroll
      for (int r = 0; r < 2; r++) {
        int f = tid + 256 * r;
        int row = f >> 4, col = (f & 15) * 4;
        cpa16(&Ks[(nb * 32 + row) * PAD + col], &Kn[row * 64 + col]);
        cpa16(&Vs[(nb * 32 + row) * PAD + col], &Vn[row * 64 + col]);
      }
      cp_commit();
      cp_wait1();
    } else {
      cp_wait0();
    }
    __syncthreads();  // stage j visible to all; all done with buf from j-1

    if (j == 0) {  // Qs just became visible; hoist fragments to registers
#pragma unroll
      for (int kk = 0; kk < 8; kk++) {
        qf[kk][0] = Qs[(mrow + g) * PAD + kk * 8 + t];
        qf[kk][1] = Qs[(mrow + g + 8) * PAD + kk * 8 + t];
        qf[kk][2] = Qs[(mrow + g) * PAD + kk * 8 + t + 4];
        qf[kk][3] = Qs[(mrow + g + 8) * PAD + kk * 8 + t + 4];
      }
    }

    const uint32_t* Kb = Ks + buf * 32 * PAD;
    const uint32_t* Vb = Vs + buf * 32 * PAD;

    // S = Q @ K^T  (128 x 32 chunk)
    float s[4][4] = {};
#pragma unroll
    for (int kk = 0; kk < 8; kk++) {
      const int k0 = kk * 8;
#pragma unroll
      for (int nt = 0; nt < 4; nt++) {
        mma_tf32(s[nt], qf[kk][0], qf[kk][1], qf[kk][2], qf[kk][3],
                 Kb[(nt * 8 + g) * PAD + k0 + t],
                 Kb[(nt * 8 + g) * PAD + k0 + t + 4]);
      }
    }

    if (j >= 4 * qi) {  // only the 4 diagonal-band tiles can clip
#pragma unroll
      for (int nt = 0; nt < 4; nt++)
#pragma unroll
        for (int i = 0; i < 4; i++) {
          int col = j * 32 + nt * 8 + 2 * t + (i & 1);
          int row = qrow0 + ((i >= 2) ? 8 : 0);
          if (col > row) s[nt][i] = -1e30f;
        }
    }

    // online softmax (log2 domain), rows warp-local, quad reduce
    float rmax0 = -1e30f, rmax1 = -1e30f;
#pragma unroll
    for (int nt = 0; nt < 4; nt++) {
      rmax0 = fmaxf(rmax0, fmaxf(s[nt][0], s[nt][1]));
      rmax1 = fmaxf(rmax1, fmaxf(s[nt][2], s[nt][3]));
    }
    rmax0 = fmaxf(rmax0, __shfl_xor_sync(0xffffffffu, rmax0, 1));
    rmax0 = fmaxf(rmax0, __shfl_xor_sync(0xffffffffu, rmax0, 2));
    rmax1 = fmaxf(rmax1, __shfl_xor_sync(0xffffffffu, rmax1, 1));
    rmax1 = fmaxf(rmax1, __shfl_xor_sync(0xffffffffu, rmax1, 2));

    float nm0 = fmaxf(m0, rmax0), nm1 = fmaxf(m1, rmax1);
    float sc0 = ex2(m0 - nm0), sc1 = ex2(m1 - nm1);
    m0 = nm0;
    m1 = nm1;

    float rs0 = 0.f, rs1 = 0.f;
#pragma unroll
    for (int nt = 0; nt < 4; nt++)
#pragma unroll
      for (int i = 0; i < 4; i++) {
        float nm = (i >= 2) ? nm1 : nm0;
        uint32_t u = f2tf(ex2(s[nt][i] - nm));
        float pf = __uint_as_float(u);  // l matches tf32-rounded P exactly
        if (i >= 2) rs1 += pf; else rs0 += pf;
        Ps[(mrow + g + ((i >= 2) ? 8 : 0)) * PAD2 + nt * 8 + 2 * t + (i & 1)] = u;
      }
    rs0 += __shfl_xor_sync(0xffffffffu, rs0, 1);
    rs0 += __shfl_xor_sync(0xffffffffu, rs0, 2);
    rs1 += __shfl_xor_sync(0xffffffffu, rs1, 1);
    rs1 += __shfl_xor_sync(0xffffffffu, rs1, 2);
    l0 = l0 * sc0 + rs0;
    l1 = l1 * sc1 + rs1;
#pragma unroll
    for (int nt = 0; nt < 8; nt++) {
      o[nt][0] *= sc0;
      o[nt][1] *= sc0;
      o[nt][2] *= sc1;
      o[nt][3] *= sc1;
    }

    __syncwarp();  // Ps rows are warp-private; order STS before LDS

    // O += P @ V  (128x32 @ 32x64)
#pragma unroll
    for (int k0 = 0; k0 < 32; k0 += 8) {
      uint32_t a0 = Ps[(mrow + g) * PAD2 + k0 + t];
      uint32_t a1 = Ps[(mrow + g + 8) * PAD2 + k0 + t];
      uint32_t a2 = Ps[(mrow + g) * PAD2 + k0 + t + 4];
      uint32_t a3 = Ps[(mrow + g + 8) * PAD2 + k0 + t + 4];
#pragma unroll
      for (int nt = 0; nt < 8; nt++) {
        mma_tf32(o[nt], a0, a1, a2, a3, Vb[(k0 + t) * PAD + nt * 8 + g],
                 Vb[(k0 + t + 4) * PAD + nt * 8 + g]);
      }
    }
    __syncthreads();  // all warps done with buf before it is refilled at j+1
  }

  const int b = bh >> 4, h = bh & 15;
  float inv0 = 1.f / l0, inv1 = 1.f / l1;
#pragma unroll
  for (int nt = 0; nt < 8; nt++)
#pragma unroll
    for (int i = 0; i < 4; i++) {
      int srow = qi * 128 + mrow + g + ((i >= 2) ? 8 : 0);
      int col = nt * 8 + 2 * t + (i & 1);
      g_Y[((size_t)b * PS + srow) * PE + h * PHD + col] =
          f2tf(o[nt][i] * ((i >= 2) ? inv1 : inv0));
    }
}

// ---------------------------------------------------------------------------
// Kernel 3: output projection. 128x128 tile/block, 256 thr, 32-deep K stages,
// cp.async double-buffered (R3 structure). Warp tile 32x64: LDS/MMA = 1.5.
// ---------------------------------------------------------------------------
__global__ __launch_bounds__(256) void proj_kernel(
    const float* __restrict__ bias, float* __restrict__ out) {
  extern __shared__ uint32_t sm[];
  uint32_t* Ys = sm;                  // 2 bufs x 128*PAD2
  uint32_t* Ws = Ys + 2 * 128 * PAD2; // 2 bufs x 128*PAD2
  const int tid = threadIdx.x;
  const int wid = tid >> 5, lane = tid & 31;
  const int g = lane >> 2, t = lane & 3;
  const int wm = wid & 3, wn = wid >> 2;  // 4(m) x 2(n)
  const int mrow = wm * 32;
  const int bm = blockIdx.y, bn = blockIdx.x;

  const uint32_t* Yg = g_Y + (size_t)bm * 128 * PE;
  const uint32_t* Wg = g_Wp + (size_t)bn * 128 * PE;

  // Prologue: stage 0
#pragma unroll
  for (int r = 0; r < 4; r++) {
    int f = tid + 256 * r;
    int row = f >> 3, col = (f & 7) * 4;
    cpa16(&Ys[row * PAD2 + col], &Yg[(size_t)row * PE + col]);
    cpa16(&Ws[row * PAD2 + col], &Wg[(size_t)row * PE + col]);
  }
  cp_commit();

  float acc[2][8][4] = {};
  const int NK = PE / 32;
  for (int kt = 0; kt < NK; kt++) {
    const int buf = kt & 1;
    if (kt + 1 < NK) {
      const int nb = (kt + 1) & 1;
      const uint32_t* Yn = Yg + (size_t)(kt + 1) * 32;
      const uint32_t* Wn = Wg + (size_t)(kt + 1) * 32;
#pragma unroll
      for (int r = 0; r < 4; r++) {
        int f = tid + 256 * r;
        int row = f >> 3, col = (f & 7) * 4;
        cpa16(&Ys[(nb * 128 + row) * PAD2 + col], &Yn[(size_t)row * PE + col]);
        cpa16(&Ws[(nb * 128 + row) * PAD2 + col], &Wn[(size_t)row * PE + col]);
      }
      cp_commit();
      cp_wait1();
    } else {
      cp_wait0();
    }
    __syncthreads();

    const uint32_t* Yb = Ys + buf * 128 * PAD2;
    const uint32_t* Wb = Ws + buf * 128 * PAD2;
#pragma unroll
    for (int k0 = 0; k0 < 32; k0 += 8) {
      uint32_t a[2][4];
#pragma unroll
      for (int mf = 0; mf < 2; mf++) {
        a[mf][0] = Yb[(mrow + mf * 16 + g) * PAD2 + k0 + t];
        a[mf][1] = Yb[(mrow + mf * 16 + 8 + g) * PAD2 + k0 + t];
        a[mf][2] = Yb[(mrow + mf * 16 + g) * PAD2 + k0 + t + 4];
        a[mf][3] = Yb[(mrow + mf * 16 + 8 + g) * PAD2 + k0 + t + 4];
      }
#pragma unroll
      for (int nt = 0; nt < 8; nt++) {
        uint32_t b0 = Wb[(wn * 64 + nt * 8 + g) * PAD2 + k0 + t];
        uint32_t b1 = Wb[(wn * 64 + nt * 8 + g) * PAD2 + k0 + t + 4];
        mma_tf32(acc[0][nt], a[0][0], a[0][1], a[0][2], a[0][3], b0, b1);
        mma_tf32(acc[1][nt], a[1][0], a[1][1], a[1][2], a[1][3], b0, b1);
      }
    }
    __syncthreads();
  }

#pragma unroll
  for (int mf = 0; mf < 2; mf++)
#pragma unroll
    for (int nt = 0; nt < 8; nt++)
#pragma unroll
      for (int i = 0; i < 4; i++) {
        int row = bm * 128 + mrow + mf * 16 + g + ((i >= 2) ? 8 : 0);
        int col = bn * 128 + wn * 64 + nt * 8 + 2 * t + (i & 1);
        out[(size_t)row * PE + col] = acc[mf][nt][i] + bias[col];
      }
}

// ---------------------------------------------------------------------------
extern "C" void kernel_launch(void* const* d_in, const int* in_sizes, int n_in,
                              void* d_out, int out_size) {
  const float* x  = (const float*)d_in[0];
  const float* Wq = (const float*)d_in[1];
  const float* bq = (const float*)d_in[2];
  const float* Wk = (const float*)d_in[3];
  const float* bk = (const float*)d_in[4];
  const float* Wv = (const float*)d_in[5];
  const float* bv = (const float*)d_in[6];
  const float* Wp = (const float*)d_in[7];
  const float* bp = (const float*)d_in[8];
  float* out = (float*)d_out;

  const int smem_qkv  = (128 + 3 * 64) * PAD * 4;                 // 87,040 B
  const int smem_attn = (128 * PAD + 128 * PAD + 128 * PAD2) * 4; // 88,064 B
  const int smem_proj = (4 * 128 * PAD2) * 4;                     // 73,728 B
  cudaFuncSetAttribute(qkv_kernel, cudaFuncAttributeMaxDynamicSharedMemorySize, smem_qkv);
  cudaFuncSetAttribute(attn_kernel, cudaFuncAttributeMaxDynamicSharedMemorySize, smem_attn);
  cudaFuncSetAttribute(proj_kernel, cudaFuncAttributeMaxDynamicSharedMemorySize, smem_proj);

  prep_kernel<<<(PE * PE + 255) / 256, 256>>>(Wp, Wq, Wk, Wv);
  qkv_kernel<<<MROWS / 128, 512, smem_qkv>>>(x, bq, bk, bv);
  attn_kernel<<<dim3(PS / 128, PB * PH), 256, smem_attn>>>();
  proj_kernel<<<dim3(PE / 128, (PB * PS) / 128), 256, smem_proj>>>(bp, out);
}

// round 6
// speedup vs baseline: 2.0049x; 1.2459x over previous
#include <cuda_runtime.h>
#include <cstdint>

#define PB 2
#define PS 2048
#define PE 1024
#define PH 16
#define PHD 64
#define MROWS (PB * PS * PH)
#define PAD 68   // qkv internal tiles (unchanged path)
#define PAD2 36  // attention P tile

// Scratch, tf32 bit patterns (allocation-free rule).
// g_Q: A-frag layout  [bh][qt 16][kc 8][rc 8][lane 32][4]
// g_K: B-frag layout  [bh][kt 64][kc 8][nc 4][lane 32][2]
// g_V: B-frag layout  [bh][vt 64][kchunk 4][nc 8][lane 32][2]
// g_Y: A-frag layout  [mt 32][kc 128][rc 8][lane 32][4]
// g_Wp: B-frag layout [nt 8][kc 128][nc 16][lane 32][2]
__device__ uint32_t g_Q[(size_t)PB * PH * PS * PHD];
__device__ uint32_t g_K[(size_t)PB * PH * PS * PHD];
__device__ uint32_t g_V[(size_t)PB * PH * PS * PHD];
__device__ uint32_t g_Y[(size_t)PB * PS * PE];
__device__ uint32_t g_Wp[(size_t)PE * PE];
__device__ uint32_t g_Wq[PHD * PHD];
__device__ uint32_t g_Wk[PHD * PHD];
__device__ uint32_t g_Wv[PHD * PHD];

__device__ __forceinline__ uint32_t f2tf(float x) {
  uint32_t u;
  asm("cvt.rna.tf32.f32 %0, %1;" : "=r"(u) : "f"(x));
  return u;
}
__device__ __forceinline__ float ex2(float x) {
  float y;
  asm("ex2.approx.ftz.f32 %0, %1;" : "=f"(y) : "f"(x));
  return y;
}
__device__ __forceinline__ void mma_tf32(float c[4], uint32_t a0, uint32_t a1,
                                         uint32_t a2, uint32_t a3, uint32_t b0,
                                         uint32_t b1) {
  asm volatile(
      "mma.sync.aligned.m16n8k8.row.col.f32.tf32.tf32.f32 "
      "{%0,%1,%2,%3}, {%4,%5,%6,%7}, {%8,%9}, {%0,%1,%2,%3};"
      : "+f"(c[0]), "+f"(c[1]), "+f"(c[2]), "+f"(c[3])
      : "r"(a0), "r"(a1), "r"(a2), "r"(a3), "r"(b0), "r"(b1));
}
__device__ __forceinline__ void cpa16(uint32_t* smem_dst, const void* gsrc) {
  uint32_t d = (uint32_t)__cvta_generic_to_shared(smem_dst);
  asm volatile("cp.async.cg.shared.global [%0], [%1], 16;" ::"r"(d), "l"(gsrc));
}
__device__ __forceinline__ void cp_commit() {
  asm volatile("cp.async.commit_group;");
}
__device__ __forceinline__ void cp_wait1() {
  asm volatile("cp.async.wait_group 1;");
}
__device__ __forceinline__ void cp_wait0() {
  asm volatile("cp.async.wait_group 0;");
}

// A-frag index within one [kc][rc][lane][4] tile set of width KCN chunks.
// row in [0,16*RCN), col in [0, 8*KCN)
__device__ __forceinline__ size_t aidx(int row, int col, int RCN) {
  int rc = row >> 4, jlo = (row >> 3) & 1, g = row & 7;
  int kc = col >> 3, t = col & 3, hi = (col >> 2) & 1;
  return ((size_t)(kc * RCN + rc) * 32 + g * 4 + t) * 4 + hi * 2 + jlo;
}
// B-frag index within one [kc][nc][lane][2] tile set.
__device__ __forceinline__ size_t bidx(int n, int k, int NCN) {
  int nc = n >> 3, g = n & 7;
  int kc = k >> 3, t = k & 3, hi = (k >> 2) & 1;
  return ((size_t)(kc * NCN + nc) * 32 + g * 4 + t) * 2 + hi;
}

// ---------------------------------------------------------------------------
// Kernel 0: one-time tf32 pre-conversion. Wp goes to B-frag layout.
// ---------------------------------------------------------------------------
__global__ __launch_bounds__(256) void prep_kernel(
    const float* __restrict__ Wp, const float* __restrict__ Wq,
    const float* __restrict__ Wk, const float* __restrict__ Wv) {
  int i = blockIdx.x * 256 + threadIdx.x;
  if (i < PE * PE) {
    int n = i >> 10, k = i & 1023;
    int nt = n >> 7;
    size_t idx = (size_t)nt * 131072 + (size_t)(k >> 3) * 1024 +
                 bidx(n & 127, k & 7, 16);
    g_Wp[idx] = f2tf(Wp[i]);
  }
  if (i < PHD * PHD) {
    g_Wq[i] = f2tf(Wq[i]);
    g_Wk[i] = f2tf(Wk[i]);
    g_Wv[i] = f2tf(Wv[i]);
  }
}

// ---------------------------------------------------------------------------
// Kernel 1: fused QKV projection (internal GEMM unchanged). Epilogue writes
// Q/K/V in fragment-order layouts. Q pre-scaled by (1/sqrt(64))*log2(e).
// ---------------------------------------------------------------------------
__global__ __launch_bounds__(512) void qkv_kernel(
    const float* __restrict__ x, const float* __restrict__ bq,
    const float* __restrict__ bk, const float* __restrict__ bv) {
  extern __shared__ uint32_t sm[];
  uint32_t* Xs = sm;               // 128*PAD
  uint32_t* Aq = Xs + 128 * PAD;   // 64*PAD each
  uint32_t* Ak = Aq + 64 * PAD;
  uint32_t* Av = Ak + 64 * PAD;
  const int tid = threadIdx.x;
  const int rowbase = blockIdx.x * 128;

#pragma unroll
  for (int r = 0; r < 2; r++) {
    int f = tid + 512 * r;
    int row = f >> 4, col = (f & 15) * 4;
    cpa16(&Aq[row * PAD + col], &g_Wq[row * 64 + col]);
    cpa16(&Ak[row * PAD + col], &g_Wk[row * 64 + col]);
    cpa16(&Av[row * PAD + col], &g_Wv[row * 64 + col]);
  }
  cp_commit();
#pragma unroll
  for (int r = 0; r < 4; r++) {
    int f = tid + 512 * r;
    int row = f >> 4, col = (f & 15) * 4;
    float4 v = *(const float4*)&x[(size_t)(rowbase + row) * 64 + col];
    uint4 u = {f2tf(v.x), f2tf(v.y), f2tf(v.z), f2tf(v.w)};
    *(uint4*)&Xs[row * PAD + col] = u;
  }
  cp_wait0();
  __syncthreads();

  const int wid = tid >> 5, lane = tid & 31;
  const int g = lane >> 2, t = lane & 3;
  const int mrow = (wid & 7) * 16;
  const int wn = wid >> 3;

  float cq[4][4] = {}, ck[4][4] = {}, cv[4][4] = {};
#pragma unroll
  for (int k0 = 0; k0 < 64; k0 += 8) {
    uint32_t a0 = Xs[(mrow + g) * PAD + k0 + t];
    uint32_t a1 = Xs[(mrow + g + 8) * PAD + k0 + t];
    uint32_t a2 = Xs[(mrow + g) * PAD + k0 + t + 4];
    uint32_t a3 = Xs[(mrow + g + 8) * PAD + k0 + t + 4];
#pragma unroll
    for (int nt = 0; nt < 4; nt++) {
      int n0 = wn * 32 + nt * 8;
      mma_tf32(cq[nt], a0, a1, a2, a3, Aq[(n0 + g) * PAD + k0 + t],
               Aq[(n0 + g) * PAD + k0 + t + 4]);
      mma_tf32(ck[nt], a0, a1, a2, a3, Ak[(n0 + g) * PAD + k0 + t],
               Ak[(n0 + g) * PAD + k0 + t + 4]);
      mma_tf32(cv[nt], a0, a1, a2, a3, Av[(n0 + g) * PAD + k0 + t],
               Av[(n0 + g) * PAD + k0 + t + 4]);
    }
  }

  const float qscale = 0.125f * 1.4426950408889634f;  // 1/sqrt(64) * log2(e)
#pragma unroll
  for (int nt = 0; nt < 4; nt++)
#pragma unroll
    for (int i = 0; i < 4; i++) {
      int row = rowbase + mrow + g + ((i >= 2) ? 8 : 0);
      int col = wn * 32 + nt * 8 + 2 * t + (i & 1);
      int b = row >> 15;              // row / (S*H)
      int s = (row >> 4) & (PS - 1);  // (row / H) % S
      int h = row & 15;
      int bh = b * PH + h;
      // Q: A-frag [bh][qt][kc 8][rc 8][lane][4]
      size_t qi_ = (size_t)(bh * 16 + (s >> 7)) * 8192 + aidx(s & 127, col, 8);
      g_Q[qi_] = f2tf((cq[nt][i] + bq[col]) * qscale);
      // K: B-frag [bh][kt 64][kc 8][nc 4][lane][2]  (n = s within 32-row tile)
      size_t ki_ = (size_t)(bh * 64 + (s >> 5)) * 2048 + bidx(s & 31, col, 4);
      g_K[ki_] = f2tf(ck[nt][i] + bk[col]);
      // V: B-frag [bh][vt 64][kchunk 4][nc 8][lane][2] (n = col, k = s)
      size_t vi_ = (size_t)(bh * 64 + (s >> 5)) * 2048 + bidx(col, s & 31, 8);
      g_V[vi_] = f2tf(cv[nt][i] + bv[col]);
    }
}

// ---------------------------------------------------------------------------
// Kernel 2: causal flash attention. 256 thr, 128 queries/block, 32-row KV
// stages double-buffered (R5 structure). Fragment-order smem: vectorized LDS.
// ---------------------------------------------------------------------------
__global__ __launch_bounds__(256) void attn_kernel() {
  extern __shared__ uint32_t sm[];
  uint32_t* Qs = sm;            // 8192: [kc 8][rc 8][lane][4]
  uint32_t* Ks = Qs + 8192;     // 2 x 2048: [kc 8][nc 4][lane][2]
  uint32_t* Vs = Ks + 4096;     // 2 x 2048: [kchunk 4][nc 8][lane][2]
  uint32_t* Ps = Vs + 4096;     // 128*PAD2
  const int tid = threadIdx.x;
  const int wid = tid >> 5, lane = tid & 31;
  const int g = lane >> 2, t = lane & 3;
  const int mrow = wid * 16;
  const int bh = blockIdx.y;
  const int qi = (PS / 128 - 1) - blockIdx.x;  // big tiles first
  const int ntiles = 4 * qi + 4;

  const uint32_t* Qg = g_Q + (size_t)(bh * 16 + qi) * 8192;
  const uint32_t* Kg = g_K + (size_t)bh * 64 * 2048;
  const uint32_t* Vg = g_V + (size_t)bh * 64 * 2048;

  // Prologue group: Q tile + KV stage 0 (all contiguous copies)
#pragma unroll
  for (int r = 0; r < 8; r++) {
    int f = tid + 256 * r;
    cpa16(&Qs[f * 4], &Qg[f * 4]);
  }
#pragma unroll
  for (int r = 0; r < 2; r++) {
    int f = tid + 256 * r;
    cpa16(&Ks[f * 4], &Kg[f * 4]);
    cpa16(&Vs[f * 4], &Vg[f * 4]);
  }
  cp_commit();

  float m0 = -1e30f, m1 = -1e30f, l0 = 0.f, l1 = 0.f;
  float o[8][4] = {};
  uint32_t qf[8][4];  // Q fragments, filled at j==0, live for the whole loop
  const int qrow0 = qi * 128 + mrow + g;

  for (int j = 0; j < ntiles; j++) {
    const int buf = j & 1;
    if (j + 1 < ntiles) {
      const int nb = (j + 1) & 1;
      const uint32_t* Kn = Kg + (size_t)(j + 1) * 2048;
      const uint32_t* Vn = Vg + (size_t)(j + 1) * 2048;
#pragma unroll
      for (int r = 0; r < 2; r++) {
        int f = tid + 256 * r;
        cpa16(&Ks[nb * 2048 + f * 4], &Kn[f * 4]);
        cpa16(&Vs[nb * 2048 + f * 4], &Vn[f * 4]);
      }
      cp_commit();
      cp_wait1();
    } else {
      cp_wait0();
    }
    __syncthreads();  // stage j visible; all done with buf from j-1

    if (j == 0) {  // hoist Q fragments: one LDS.128 per k-chunk
#pragma unroll
      for (int kc = 0; kc < 8; kc++) {
        uint4 q4 = *(const uint4*)&Qs[((kc * 8 + wid) * 32 + lane) * 4];
        qf[kc][0] = q4.x;
        qf[kc][1] = q4.y;
        qf[kc][2] = q4.z;
        qf[kc][3] = q4.w;
      }
    }

    const uint32_t* Kb = Ks + buf * 2048;
    const uint32_t* Vb = Vs + buf * 2048;

    // S = Q @ K^T  (128 x 32 chunk); B frags via LDS.64
    float s[4][4] = {};
#pragma unroll
    for (int kc = 0; kc < 8; kc++) {
#pragma unroll
      for (int nt = 0; nt < 4; nt++) {
        uint2 kb = *(const uint2*)&Kb[((kc * 4 + nt) * 32 + lane) * 2];
        mma_tf32(s[nt], qf[kc][0], qf[kc][1], qf[kc][2], qf[kc][3], kb.x, kb.y);
      }
    }

    if (j >= 4 * qi) {  // only the 4 diagonal-band tiles can clip
#pragma unroll
      for (int nt = 0; nt < 4; nt++)
#pragma unroll
        for (int i = 0; i < 4; i++) {
          int col = j * 32 + nt * 8 + 2 * t + (i & 1);
          int row = qrow0 + ((i >= 2) ? 8 : 0);
          if (col > row) s[nt][i] = -1e30f;
        }
    }

    // online softmax (log2 domain), rows warp-local, quad reduce
    float rmax0 = -1e30f, rmax1 = -1e30f;
#pragma unroll
    for (int nt = 0; nt < 4; nt++) {
      rmax0 = fmaxf(rmax0, fmaxf(s[nt][0], s[nt][1]));
      rmax1 = fmaxf(rmax1, fmaxf(s[nt][2], s[nt][3]));
    }
    rmax0 = fmaxf(rmax0, __shfl_xor_sync(0xffffffffu, rmax0, 1));
    rmax0 = fmaxf(rmax0, __shfl_xor_sync(0xffffffffu, rmax0, 2));
    rmax1 = fmaxf(rmax1, __shfl_xor_sync(0xffffffffu, rmax1, 1));
    rmax1 = fmaxf(rmax1, __shfl_xor_sync(0xffffffffu, rmax1, 2));

    float nm0 = fmaxf(m0, rmax0), nm1 = fmaxf(m1, rmax1);
    float sc0 = ex2(m0 - nm0), sc1 = ex2(m1 - nm1);
    m0 = nm0;
    m1 = nm1;

    float rs0 = 0.f, rs1 = 0.f;
#pragma unroll
    for (int nt = 0; nt < 4; nt++)
#pragma unroll
      for (int i = 0; i < 4; i++) {
        float nm = (i >= 2) ? nm1 : nm0;
        uint32_t u = f2tf(ex2(s[nt][i] - nm));
        float pf = __uint_as_float(u);  // l matches tf32-rounded P exactly
        if (i >= 2) rs1 += pf; else rs0 += pf;
        Ps[(mrow + g + ((i >= 2) ? 8 : 0)) * PAD2 + nt * 8 + 2 * t + (i & 1)] = u;
      }
    rs0 += __shfl_xor_sync(0xffffffffu, rs0, 1);
    rs0 += __shfl_xor_sync(0xffffffffu, rs0, 2);
    rs1 += __shfl_xor_sync(0xffffffffu, rs1, 1);
    rs1 += __shfl_xor_sync(0xffffffffu, rs1, 2);
    l0 = l0 * sc0 + rs0;
    l1 = l1 * sc1 + rs1;
#pragma unroll
    for (int nt = 0; nt < 8; nt++) {
      o[nt][0] *= sc0;
      o[nt][1] *= sc0;
      o[nt][2] *= sc1;
      o[nt][3] *= sc1;
    }

    __syncwarp();  // Ps rows are warp-private; order STS before LDS

    // O += P @ V  (128x32 @ 32x64); V frags via LDS.64
#pragma unroll
    for (int k0 = 0; k0 < 32; k0 += 8) {
      uint32_t a0 = Ps[(mrow + g) * PAD2 + k0 + t];
      uint32_t a1 = Ps[(mrow + g + 8) * PAD2 + k0 + t];
      uint32_t a2 = Ps[(mrow + g) * PAD2 + k0 + t + 4];
      uint32_t a3 = Ps[(mrow + g + 8) * PAD2 + k0 + t + 4];
#pragma unroll
      for (int nt = 0; nt < 8; nt++) {
        uint2 vb = *(const uint2*)&Vb[(((k0 >> 3) * 8 + nt) * 32 + lane) * 2];
        mma_tf32(o[nt], a0, a1, a2, a3, vb.x, vb.y);
      }
    }
    __syncthreads();  // all warps done with buf before refill at j+1
  }

  const int b = bh >> 4, h = bh & 15;
  float inv0 = 1.f / l0, inv1 = 1.f / l1;
#pragma unroll
  for (int nt = 0; nt < 8; nt++)
#pragma unroll
    for (int i = 0; i < 4; i++) {
      int srow = qi * 128 + mrow + g + ((i >= 2) ? 8 : 0);
      int col = nt * 8 + 2 * t + (i & 1);
      int row = b * PS + srow;       // logical Y row in [0,4096)
      int e = h * PHD + col;         // logical Y col in [0,1024)
      // Y: A-frag [mt 32][kc 128][rc 8][lane][4]
      size_t yi_ = (size_t)(row >> 7) * 131072 + (size_t)(e >> 3) * 1024 +
                   aidx(row & 127, e & 7, 8);
      g_Y[yi_] = f2tf(o[nt][i] * ((i >= 2) ? inv1 : inv0));
    }
}

// ---------------------------------------------------------------------------
// Kernel 3: output projection. 128x128 tile/block, 256 thr, 32-deep K stages
// double-buffered. Fragment-order smem: A via LDS.128, B via LDS.64.
// ---------------------------------------------------------------------------
__global__ __launch_bounds__(256) void proj_kernel(
    const float* __restrict__ bias, float* __restrict__ out) {
  extern __shared__ uint32_t sm[];
  uint32_t* Ys = sm;            // 2 x 4096: [kc 4][rc 8][lane][4]
  uint32_t* Ws = Ys + 8192;     // 2 x 4096: [kc 4][nc 16][lane][2]
  const int tid = threadIdx.x;
  const int wid = tid >> 5, lane = tid & 31;
  const int g = lane >> 2, t = lane & 3;
  const int wm = wid & 3, wn = wid >> 2;  // 4(m) x 2(n)
  const int bm = blockIdx.y, bn = blockIdx.x;

  const uint32_t* Yg = g_Y + (size_t)bm * 131072;
  const uint32_t* Wg = g_Wp + (size_t)bn * 131072;

  // Prologue: stage 0 (contiguous 4096-word blocks)
#pragma unroll
  for (int r = 0; r < 4; r++) {
    int f = tid + 256 * r;
    cpa16(&Ys[f * 4], &Yg[f * 4]);
    cpa16(&Ws[f * 4], &Wg[f * 4]);
  }
  cp_commit();

  float acc[2][8][4] = {};
  const int NK = PE / 32;
  for (int kt = 0; kt < NK; kt++) {
    const int buf = kt & 1;
    if (kt + 1 < NK) {
      const int nb = (kt + 1) & 1;
      const uint32_t* Yn = Yg + (size_t)(kt + 1) * 4096;
      const uint32_t* Wn = Wg + (size_t)(kt + 1) * 4096;
#pragma unroll
      for (int r = 0; r < 4; r++) {
        int f = tid + 256 * r;
        cpa16(&Ys[nb * 4096 + f * 4], &Yn[f * 4]);
        cpa16(&Ws[nb * 4096 + f * 4], &Wn[f * 4]);
      }
      cp_commit();
      cp_wait1();
    } else {
      cp_wait0();
    }
    __syncthreads();

    const uint32_t* Yb = Ys + buf * 4096;
    const uint32_t* Wb = Ws + buf * 4096;
#pragma unroll
    for (int kc = 0; kc < 4; kc++) {
      uint4 a[2];
#pragma unroll
      for (int mf = 0; mf < 2; mf++)
        a[mf] = *(const uint4*)&Yb[((kc * 8 + wm * 2 + mf) * 32 + lane) * 4];
#pragma unroll
      for (int nt = 0; nt < 8; nt++) {
        uint2 b2 = *(const uint2*)&Wb[((kc * 16 + wn * 8 + nt) * 32 + lane) * 2];
        mma_tf32(acc[0][nt], a[0].x, a[0].y, a[0].z, a[0].w, b2.x, b2.y);
        mma_tf32(acc[1][nt], a[1].x, a[1].y, a[1].z, a[1].w, b2.x, b2.y);
      }
    }
    __syncthreads();
  }

#pragma unroll
  for (int mf = 0; mf < 2; mf++)
#pragma unroll
    for (int nt = 0; nt < 8; nt++) {
      int col = bn * 128 + wn * 64 + nt * 8 + 2 * t;
      int row0 = bm * 128 + wm * 32 + mf * 16 + g;
      float2 v0 = {acc[mf][nt][0] + bias[col], acc[mf][nt][1] + bias[col + 1]};
      float2 v1 = {acc[mf][nt][2] + bias[col], acc[mf][nt][3] + bias[col + 1]};
      *(float2*)&out[(size_t)row0 * PE + col] = v0;
      *(float2*)&out[(size_t)(row0 + 8) * PE + col] = v1;
    }
}

// ---------------------------------------------------------------------------
extern "C" void kernel_launch(void* const* d_in, const int* in_sizes, int n_in,
                              void* d_out, int out_size) {
  const float* x  = (const float*)d_in[0];
  const float* Wq = (const float*)d_in[1];
  const float* bq = (const float*)d_in[2];
  const float* Wk = (const float*)d_in[3];
  const float* bk = (const float*)d_in[4];
  const float* Wv = (const float*)d_in[5];
  const float* bv = (const float*)d_in[6];
  const float* Wp = (const float*)d_in[7];
  const float* bp = (const float*)d_in[8];
  float* out = (float*)d_out;

  const int smem_qkv  = (128 + 3 * 64) * PAD * 4;            // 87,040 B
  const int smem_attn = (8192 + 4096 + 4096 + 128 * PAD2) * 4;  // 83,968 B
  const int smem_proj = 16384 * 4;                            // 65,536 B
  cudaFuncSetAttribute(qkv_kernel, cudaFuncAttributeMaxDynamicSharedMemorySize, smem_qkv);
  cudaFuncSetAttribute(attn_kernel, cudaFuncAttributeMaxDynamicSharedMemorySize, smem_attn);
  cudaFuncSetAttribute(proj_kernel, cudaFuncAttributeMaxDynamicSharedMemorySize, smem_proj);

  prep_kernel<<<(PE * PE + 255) / 256, 256>>>(Wp, Wq, Wk, Wv);
  qkv_kernel<<<MROWS / 128, 512, smem_qkv>>>(x, bq, bk, bv);
  attn_kernel<<<dim3(PS / 128, PB * PH), 256, smem_attn>>>();
  proj_kernel<<<dim3(PE / 128, (PB * PS) / 128), 256, smem_proj>>>(bp, out);
}

// round 8
// speedup vs baseline: 2.3216x; 1.1579x over previous
#include <cuda_runtime.h>
#include <cstdint>

#define PB 2
#define PS 2048
#define PE 1024
#define PH 16
#define PHD 64
#define MROWS (PB * PS * PH)
#define PAD 68   // qkv internal tiles

// Scratch, tf32 bit patterns (allocation-free rule).
// g_Q: A-frag layout  [bh][qt 16][kc 8][rc 8][lane 32][4]
// g_K: B-frag layout  [bh][kt 64][kc 8][nc 4][lane 32][2]
// g_V: B-frag layout  [bh][vt 64][kchunk 4][nc 8][lane 32][2]
// g_Y: A-frag layout  [mt 32][kc 128][rc 8][lane 32][4]
// g_Wp: B-frag layout [nt 8][kc 128][nc 16][lane 32][2]
__device__ uint32_t g_Q[(size_t)PB * PH * PS * PHD];
__device__ uint32_t g_K[(size_t)PB * PH * PS * PHD];
__device__ uint32_t g_V[(size_t)PB * PH * PS * PHD];
__device__ uint32_t g_Y[(size_t)PB * PS * PE];
__device__ uint32_t g_Wp[(size_t)PE * PE];

__device__ __forceinline__ uint32_t f2tf(float x) {
  uint32_t u;
  asm("cvt.rna.tf32.f32 %0, %1;" : "=r"(u) : "f"(x));
  return u;
}
__device__ __forceinline__ float ex2(float x) {
  float y;
  asm("ex2.approx.ftz.f32 %0, %1;" : "=f"(y) : "f"(x));
  return y;
}
__device__ __forceinline__ void mma_tf32(float c[4], uint32_t a0, uint32_t a1,
                                         uint32_t a2, uint32_t a3, uint32_t b0,
                                         uint32_t b1) {
  asm volatile(
      "mma.sync.aligned.m16n8k8.row.col.f32.tf32.tf32.f32 "
      "{%0,%1,%2,%3}, {%4,%5,%6,%7}, {%8,%9}, {%0,%1,%2,%3};"
      : "+f"(c[0]), "+f"(c[1]), "+f"(c[2]), "+f"(c[3])
      : "r"(a0), "r"(a1), "r"(a2), "r"(a3), "r"(b0), "r"(b1));
}
__device__ __forceinline__ void cpa16(uint32_t* smem_dst, const void* gsrc) {
  uint32_t d = (uint32_t)__cvta_generic_to_shared(smem_dst);
  asm volatile("cp.async.cg.shared.global [%0], [%1], 16;" ::"r"(d), "l"(gsrc));
}
__device__ __forceinline__ void cp_commit() {
  asm volatile("cp.async.commit_group;");
}
__device__ __forceinline__ void cp_wait1() {
  asm volatile("cp.async.wait_group 1;");
}
__device__ __forceinline__ void cp_wait0() {
  asm volatile("cp.async.wait_group 0;");
}

// A-frag index within one [kc][rc][lane][4] tile set, RCN row-chunks tall.
__device__ __forceinline__ size_t aidx(int row, int col, int RCN) {
  int rc = row >> 4, jlo = (row >> 3) & 1, g = row & 7;
  int kc = col >> 3, t = col & 3, hi = (col >> 2) & 1;
  return ((size_t)(kc * RCN + rc) * 32 + g * 4 + t) * 4 + hi * 2 + jlo;
}
// B-frag index within one [kc][nc][lane][2] tile set, NCN col-chunks wide.
__device__ __forceinline__ size_t bidx(int n, int k, int NCN) {
  int nc = n >> 3, g = n & 7;
  int kc = k >> 3, t = k & 3, hi = (k >> 2) & 1;
  return ((size_t)(kc * NCN + nc) * 32 + g * 4 + t) * 2 + hi;
}

// ---------------------------------------------------------------------------
// Kernel 1: fused QKV projection + (extra blocks) Wp fragment conversion.
// Blocks [0,512): qkv on 128 rows each (512*128 = MROWS), weights inline.
// Blocks [512,1024): convert Wp (fp32 -> tf32 B-frag layout), overlapped.
// ---------------------------------------------------------------------------
__global__ __launch_bounds__(512) void qkv_kernel(
    const float* __restrict__ x,
    const float* __restrict__ Wq, const float* __restrict__ Wk,
    const float* __restrict__ Wv, const float* __restrict__ Wp,
    const float* __restrict__ bq, const float* __restrict__ bk,
    const float* __restrict__ bv) {
  const int tid = threadIdx.x;

  if (blockIdx.x >= 512) {  // Wp conversion blocks: 2048 elems each
    int base = (blockIdx.x - 512) * 2048 + tid * 4;
    float4 w4 = *(const float4*)&Wp[base];
    int n = base >> 10, k = base & 1023;
    size_t o0 = (size_t)(n >> 7) * 131072 + (size_t)(k >> 3) * 1024;
    g_Wp[o0 + bidx(n & 127, k & 7, 16)] = f2tf(w4.x);
    g_Wp[o0 + bidx(n & 127, (k + 1) & 7, 16)] = f2tf(w4.y);
    g_Wp[o0 + bidx(n & 127, (k + 2) & 7, 16)] = f2tf(w4.z);
    g_Wp[o0 + bidx(n & 127, (k + 3) & 7, 16)] = f2tf(w4.w);
    return;
  }

  extern __shared__ uint32_t sm[];
  uint32_t* Xs = sm;               // 128*PAD
  uint32_t* Aq = Xs + 128 * PAD;   // 64*PAD each
  uint32_t* Ak = Aq + 64 * PAD;
  uint32_t* Av = Ak + 64 * PAD;
  const int rowbase = blockIdx.x * 128;

  // Weights: fp32 -> tf32 inline (each block reads the same 48KB; L2-hot)
#pragma unroll
  for (int r = 0; r < 2; r++) {
    int f = tid + 512 * r;
    int row = f >> 4, col = (f & 15) * 4;
    float4 q4 = *(const float4*)&Wq[row * 64 + col];
    float4 k4 = *(const float4*)&Wk[row * 64 + col];
    float4 v4 = *(const float4*)&Wv[row * 64 + col];
    uint4 uq = {f2tf(q4.x), f2tf(q4.y), f2tf(q4.z), f2tf(q4.w)};
    uint4 uk = {f2tf(k4.x), f2tf(k4.y), f2tf(k4.z), f2tf(k4.w)};
    uint4 uv = {f2tf(v4.x), f2tf(v4.y), f2tf(v4.z), f2tf(v4.w)};
    *(uint4*)&Aq[row * PAD + col] = uq;
    *(uint4*)&Ak[row * PAD + col] = uk;
    *(uint4*)&Av[row * PAD + col] = uv;
  }
#pragma unroll
  for (int r = 0; r < 4; r++) {
    int f = tid + 512 * r;
    int row = f >> 4, col = (f & 15) * 4;
    float4 v = *(const float4*)&x[(size_t)(rowbase + row) * 64 + col];
    uint4 u = {f2tf(v.x), f2tf(v.y), f2tf(v.z), f2tf(v.w)};
    *(uint4*)&Xs[row * PAD + col] = u;
  }
  __syncthreads();

  const int wid = tid >> 5, lane = tid & 31;
  const int g = lane >> 2, t = lane & 3;
  const int mrow = (wid & 7) * 16;
  const int wn = wid >> 3;

  float cq[4][4] = {}, ck[4][4] = {}, cv[4][4] = {};
#pragma unroll
  for (int k0 = 0; k0 < 64; k0 += 8) {
    uint32_t a0 = Xs[(mrow + g) * PAD + k0 + t];
    uint32_t a1 = Xs[(mrow + g + 8) * PAD + k0 + t];
    uint32_t a2 = Xs[(mrow + g) * PAD + k0 + t + 4];
    uint32_t a3 = Xs[(mrow + g + 8) * PAD + k0 + t + 4];
#pragma unroll
    for (int nt = 0; nt < 4; nt++) {
      int n0 = wn * 32 + nt * 8;
      mma_tf32(cq[nt], a0, a1, a2, a3, Aq[(n0 + g) * PAD + k0 + t],
               Aq[(n0 + g) * PAD + k0 + t + 4]);
      mma_tf32(ck[nt], a0, a1, a2, a3, Ak[(n0 + g) * PAD + k0 + t],
               Ak[(n0 + g) * PAD + k0 + t + 4]);
      mma_tf32(cv[nt], a0, a1, a2, a3, Av[(n0 + g) * PAD + k0 + t],
               Av[(n0 + g) * PAD + k0 + t + 4]);
    }
  }

  const float qscale = 0.125f * 1.4426950408889634f;  // 1/sqrt(64) * log2(e)
#pragma unroll
  for (int nt = 0; nt < 4; nt++)
#pragma unroll
    for (int i = 0; i < 4; i++) {
      int row = rowbase + mrow + g + ((i >= 2) ? 8 : 0);
      int col = wn * 32 + nt * 8 + 2 * t + (i & 1);
      int b = row >> 15;              // row / (S*H)
      int s = (row >> 4) & (PS - 1);  // (row / H) % S
      int h = row & 15;
      int bh = b * PH + h;
      size_t qi_ = (size_t)(bh * 16 + (s >> 7)) * 8192 + aidx(s & 127, col, 8);
      g_Q[qi_] = f2tf((cq[nt][i] + bq[col]) * qscale);
      size_t ki_ = (size_t)(bh * 64 + (s >> 5)) * 2048 + bidx(s & 31, col, 4);
      g_K[ki_] = f2tf(ck[nt][i] + bk[col]);
      size_t vi_ = (size_t)(bh * 64 + (s >> 5)) * 2048 + bidx(col, s & 31, 8);
      g_V[vi_] = f2tf(cv[nt][i] + bv[col]);
    }
}

// ---------------------------------------------------------------------------
// Kernel 2: causal flash attention. 256 thr. Each block processes TWO query
// tiles (qi = 15-a then a): every block = exactly 68 KV stages -> one
// balanced wave of 256 blocks. P fed to PV mma via quad shuffles (no smem).
// ---------------------------------------------------------------------------
__global__ __launch_bounds__(256) void attn_kernel() {
  extern __shared__ uint32_t sm[];
  uint32_t* Qs = sm;            // 8192: [kc 8][rc 8][lane][4]
  uint32_t* Ks = Qs + 8192;     // 2 x 2048: [kc 8][nc 4][lane][2]
  uint32_t* Vs = Ks + 4096;     // 2 x 2048: [kchunk 4][nc 8][lane][2]
  const int tid = threadIdx.x;
  const int wid = tid >> 5, lane = tid & 31;
  const int g = lane >> 2, t = lane & 3;
  const int mrow = wid * 16;
  const int bh = blockIdx.y;

  const uint32_t* Kg = g_K + (size_t)bh * 64 * 2048;
  const uint32_t* Vg = g_V + (size_t)bh * 64 * 2048;
  const int src0 = (lane & ~3) + (t >> 1);  // quad-shuffle sources for P
  const int src1 = src0 + 2;
  const bool odd = t & 1;

#pragma unroll 1
  for (int sub = 0; sub < 2; sub++) {
    const int qi = sub ? blockIdx.x : 15 - blockIdx.x;
    const int ntiles = 4 * qi + 4;
    if (sub) __syncthreads();  // all warps done with KV bufs of sub 0

    const uint32_t* Qg = g_Q + (size_t)(bh * 16 + qi) * 8192;
    // Prologue group: Q tile + KV stage 0 (contiguous copies)
#pragma unroll
    for (int r = 0; r < 8; r++) {
      int f = tid + 256 * r;
      cpa16(&Qs[f * 4], &Qg[f * 4]);
    }
#pragma unroll
    for (int r = 0; r < 2; r++) {
      int f = tid + 256 * r;
      cpa16(&Ks[f * 4], &Kg[f * 4]);
      cpa16(&Vs[f * 4], &Vg[f * 4]);
    }
    cp_commit();

    float m0 = -1e30f, m1 = -1e30f, l0 = 0.f, l1 = 0.f;
    float o[8][4] = {};
    uint32_t qf[8][4];
    const int qrow0 = qi * 128 + mrow + g;

    for (int j = 0; j < ntiles; j++) {
      const int buf = j & 1;
      if (j + 1 < ntiles) {
        const int nb = (j + 1) & 1;
        const uint32_t* Kn = Kg + (size_t)(j + 1) * 2048;
        const uint32_t* Vn = Vg + (size_t)(j + 1) * 2048;
#pragma unroll
        for (int r = 0; r < 2; r++) {
          int f = tid + 256 * r;
          cpa16(&Ks[nb * 2048 + f * 4], &Kn[f * 4]);
          cpa16(&Vs[nb * 2048 + f * 4], &Vn[f * 4]);
        }
        cp_commit();
        cp_wait1();
      } else {
        cp_wait0();
      }
      __syncthreads();  // stage j visible; all done with buf from j-1

      if (j == 0) {  // hoist Q fragments: one LDS.128 per k-chunk
#pragma unroll
        for (int kc = 0; kc < 8; kc++) {
          uint4 q4 = *(const uint4*)&Qs[((kc * 8 + wid) * 32 + lane) * 4];
          qf[kc][0] = q4.x;
          qf[kc][1] = q4.y;
          qf[kc][2] = q4.z;
          qf[kc][3] = q4.w;
        }
      }

      const uint32_t* Kb = Ks + buf * 2048;
      const uint32_t* Vb = Vs + buf * 2048;

      // S = Q @ K^T  (128 x 32 chunk)
      float s[4][4] = {};
#pragma unroll
      for (int kc = 0; kc < 8; kc++) {
#pragma unroll
        for (int nt = 0; nt < 4; nt++) {
          uint2 kb = *(const uint2*)&Kb[((kc * 4 + nt) * 32 + lane) * 2];
          mma_tf32(s[nt], qf[kc][0], qf[kc][1], qf[kc][2], qf[kc][3], kb.x,
                   kb.y);
        }
      }

      if (j >= 4 * qi) {  // only the 4 diagonal-band tiles can clip
#pragma unroll
        for (int nt = 0; nt < 4; nt++)
#pragma unroll
          for (int i = 0; i < 4; i++) {
            int col = j * 32 + nt * 8 + 2 * t + (i & 1);
            int row = qrow0 + ((i >= 2) ? 8 : 0);
            if (col > row) s[nt][i] = -1e30f;
          }
      }

      // online softmax (log2 domain), rows warp-local, quad reduce
      float rmax0 = -1e30f, rmax1 = -1e30f;
#pragma unroll
      for (int nt = 0; nt < 4; nt++) {
        rmax0 = fmaxf(rmax0, fmaxf(s[nt][0], s[nt][1]));
        rmax1 = fmaxf(rmax1, fmaxf(s[nt][2], s[nt][3]));
      }
      rmax0 = fmaxf(rmax0, __shfl_xor_sync(0xffffffffu, rmax0, 1));
      rmax0 = fmaxf(rmax0, __shfl_xor_sync(0xffffffffu, rmax0, 2));
      rmax1 = fmaxf(rmax1, __shfl_xor_sync(0xffffffffu, rmax1, 1));
      rmax1 = fmaxf(rmax1, __shfl_xor_sync(0xffffffffu, rmax1, 2));

      float nm0 = fmaxf(m0, rmax0), nm1 = fmaxf(m1, rmax1);
      float sc0 = ex2(m0 - nm0), sc1 = ex2(m1 - nm1);
      m0 = nm0;
      m1 = nm1;

      float rs0 = 0.f, rs1 = 0.f;
#pragma unroll
      for (int nt = 0; nt < 4; nt++)
#pragma unroll
        for (int i = 0; i < 4; i++) {
          float nm = (i >= 2) ? nm1 : nm0;
          float pf = __uint_as_float(f2tf(ex2(s[nt][i] - nm)));
          s[nt][i] = pf;  // tf32-rounded P, reused as mma operand via shuffle
          if (i >= 2) rs1 += pf; else rs0 += pf;
        }
      rs0 += __shfl_xor_sync(0xffffffffu, rs0, 1);
      rs0 += __shfl_xor_sync(0xffffffffu, rs0, 2);
      rs1 += __shfl_xor_sync(0xffffffffu, rs1, 1);
      rs1 += __shfl_xor_sync(0xffffffffu, rs1, 2);
      l0 = l0 * sc0 + rs0;
      l1 = l1 * sc1 + rs1;
#pragma unroll
      for (int nt = 0; nt < 8; nt++) {
        o[nt][0] *= sc0;
        o[nt][1] *= sc0;
        o[nt][2] *= sc1;
        o[nt][3] *= sc1;
      }

      // O += P @ V : P A-fragments built from s[] by quad shuffles.
      // C-frag (cols 2t,2t+1) -> A-frag (cols t,t+4): src lanes g*4+t/2 (+2).
#pragma unroll
      for (int kc = 0; kc < 4; kc++) {
        float x00 = __shfl_sync(0xffffffffu, s[kc][0], src0);
        float x01 = __shfl_sync(0xffffffffu, s[kc][1], src0);
        float x20 = __shfl_sync(0xffffffffu, s[kc][0], src1);
        float x21 = __shfl_sync(0xffffffffu, s[kc][1], src1);
        float x10 = __shfl_sync(0xffffffffu, s[kc][2], src0);
        float x11 = __shfl_sync(0xffffffffu, s[kc][3], src0);
        float x30 = __shfl_sync(0xffffffffu, s[kc][2], src1);
        float x31 = __shfl_sync(0xffffffffu, s[kc][3], src1);
        uint32_t a0 = __float_as_uint(odd ? x01 : x00);
        uint32_t a2 = __float_as_uint(odd ? x21 : x20);
        uint32_t a1 = __float_as_uint(odd ? x11 : x10);
        uint32_t a3 = __float_as_uint(odd ? x31 : x30);
#pragma unroll
        for (int nt = 0; nt < 8; nt++) {
          uint2 vb = *(const uint2*)&Vb[((kc * 8 + nt) * 32 + lane) * 2];
          mma_tf32(o[nt], a0, a1, a2, a3, vb.x, vb.y);
        }
      }
      __syncthreads();  // all warps done with buf before refill at j+1
    }

    const int b = bh >> 4, h = bh & 15;
    float inv0 = 1.f / l0, inv1 = 1.f / l1;
#pragma unroll
    for (int nt = 0; nt < 8; nt++)
#pragma unroll
      for (int i = 0; i < 4; i++) {
        int srow = qi * 128 + mrow + g + ((i >= 2) ? 8 : 0);
        int col = nt * 8 + 2 * t + (i & 1);
        int row = b * PS + srow;  // logical Y row
        int e = h * PHD + col;    // logical Y col
        size_t yi_ = (size_t)(row >> 7) * 131072 + (size_t)(e >> 3) * 1024 +
                     aidx(row & 127, e & 7, 8);
        g_Y[yi_] = f2tf(o[nt][i] * ((i >= 2) ? inv1 : inv0));
      }
  }
}

// ---------------------------------------------------------------------------
// Kernel 3: output projection. 128x128 tile/block, 256 thr, 32-deep K stages
// double-buffered. Fragment-order smem: A via LDS.128, B via LDS.64.
// ---------------------------------------------------------------------------
__global__ __launch_bounds__(256) void proj_kernel(
    const float* __restrict__ bias, float* __restrict__ out) {
  extern __shared__ uint32_t sm[];
  uint32_t* Ys = sm;            // 2 x 4096: [kc 4][rc 8][lane][4]
  uint32_t* Ws = Ys + 8192;     // 2 x 4096: [kc 4][nc 16][lane][2]
  const int tid = threadIdx.x;
  const int wid = tid >> 5, lane = tid & 31;
  const int g = lane >> 2, t = lane & 3;
  const int wm = wid & 3, wn = wid >> 2;  // 4(m) x 2(n)
  const int bm = blockIdx.y, bn = blockIdx.x;

  const uint32_t* Yg = g_Y + (size_t)bm * 131072;
  const uint32_t* Wg = g_Wp + (size_t)bn * 131072;

#pragma unroll
  for (int r = 0; r < 4; r++) {
    int f = tid + 256 * r;
    cpa16(&Ys[f * 4], &Yg[f * 4]);
    cpa16(&Ws[f * 4], &Wg[f * 4]);
  }
  cp_commit();

  float acc[2][8][4] = {};
  const int NK = PE / 32;
  for (int kt = 0; kt < NK; kt++) {
    const int buf = kt & 1;
    if (kt + 1 < NK) {
      const int nb = (kt + 1) & 1;
      const uint32_t* Yn = Yg + (size_t)(kt + 1) * 4096;
      const uint32_t* Wn = Wg + (size_t)(kt + 1) * 4096;
#pragma unroll
      for (int r = 0; r < 4; r++) {
        int f = tid + 256 * r;
        cpa16(&Ys[nb * 4096 + f * 4], &Yn[f * 4]);
        cpa16(&Ws[nb * 4096 + f * 4], &Wn[f * 4]);
      }
      cp_commit();
      cp_wait1();
    } else {
      cp_wait0();
    }
    __syncthreads();

    const uint32_t* Yb = Ys + buf * 4096;
    const uint32_t* Wb = Ws + buf * 4096;
#pragma unroll
    for (int kc = 0; kc < 4; kc++) {
      uint4 a[2];
#pragma unroll
      for (int mf = 0; mf < 2; mf++)
        a[mf] = *(const uint4*)&Yb[((kc * 8 + wm * 2 + mf) * 32 + lane) * 4];
#pragma unroll
      for (int nt = 0; nt < 8; nt++) {
        uint2 b2 = *(const uint2*)&Wb[((kc * 16 + wn * 8 + nt) * 32 + lane) * 2];
        mma_tf32(acc[0][nt], a[0].x, a[0].y, a[0].z, a[0].w, b2.x, b2.y);
        mma_tf32(acc[1][nt], a[1].x, a[1].y, a[1].z, a[1].w, b2.x, b2.y);
      }
    }
    __syncthreads();
  }

#pragma unroll
  for (int mf = 0; mf < 2; mf++)
#pragma unroll
    for (int nt = 0; nt < 8; nt++) {
      int col = bn * 128 + wn * 64 + nt * 8 + 2 * t;
      int row0 = bm * 128 + wm * 32 + mf * 16 + g;
      float2 v0 = {acc[mf][nt][0] + bias[col], acc[mf][nt][1] + bias[col + 1]};
      float2 v1 = {acc[mf][nt][2] + bias[col], acc[mf][nt][3] + bias[col + 1]};
      *(float2*)&out[(size_t)row0 * PE + col] = v0;
      *(float2*)&out[(size_t)(row0 + 8) * PE + col] = v1;
    }
}

// ---------------------------------------------------------------------------
extern "C" void kernel_launch(void* const* d_in, const int* in_sizes, int n_in,
                              void* d_out, int out_size) {
  const float* x  = (const float*)d_in[0];
  const float* Wq = (const float*)d_in[1];
  const float* bq = (const float*)d_in[2];
  const float* Wk = (const float*)d_in[3];
  const float* bk = (const float*)d_in[4];
  const float* Wv = (const float*)d_in[5];
  const float* bv = (const float*)d_in[6];
  const float* Wp = (const float*)d_in[7];
  const float* bp = (const float*)d_in[8];
  float* out = (float*)d_out;

  const int smem_qkv  = (128 + 3 * 64) * PAD * 4;        // 87,040 B
  const int smem_attn = (8192 + 4096 + 4096) * 4;        // 65,536 B
  const int smem_proj = 16384 * 4;                       // 65,536 B
  cudaFuncSetAttribute(qkv_kernel, cudaFuncAttributeMaxDynamicSharedMemorySize, smem_qkv);
  cudaFuncSetAttribute(attn_kernel, cudaFuncAttributeMaxDynamicSharedMemorySize, smem_attn);
  cudaFuncSetAttribute(proj_kernel, cudaFuncAttributeMaxDynamicSharedMemorySize, smem_proj);

  qkv_kernel<<<512 + 512, 512, smem_qkv>>>(x, Wq, Wk, Wv, Wp, bq, bk, bv);
  attn_kernel<<<dim3(8, PB * PH), 256, smem_attn>>>();
  proj_kernel<<<dim3(PE / 128, (PB * PS) / 128), 256, smem_proj>>>(bp, out);
}

// round 9
// speedup vs baseline: 2.4591x; 1.0593x over previous
#include <cuda_runtime.h>
#include <cstdint>

#define PB 2
#define PS 2048
#define PE 1024
#define PH 16
#define PHD 64
#define MROWS (PB * PS * PH)
#define PAD 68   // qkv internal tiles

// Scratch, tf32 bit patterns (allocation-free rule).
// g_Q: A-frag layout  [bh][qt 16][kc 8][rc 8][lane 32][4]
// g_K: B-frag layout  [bh][kt 64][kc 8][nc 4][lane 32][2]
// g_V: B-frag layout  [bh][vt 64][kchunk 4][nc 8][lane 32][2]
// g_Y: A-frag layout  [mt 32][kc 128][rc 8][lane 32][4]
// g_Wp: B-frag layout [nt 8][kc 128][nc 16][lane 32][2]
__device__ uint32_t g_Q[(size_t)PB * PH * PS * PHD];
__device__ uint32_t g_K[(size_t)PB * PH * PS * PHD];
__device__ uint32_t g_V[(size_t)PB * PH * PS * PHD];
__device__ uint32_t g_Y[(size_t)PB * PS * PE];
__device__ uint32_t g_Wp[(size_t)PE * PE];

__device__ __forceinline__ uint32_t f2tf(float x) {
  uint32_t u;
  asm("cvt.rna.tf32.f32 %0, %1;" : "=r"(u) : "f"(x));
  return u;
}
__device__ __forceinline__ float ex2(float x) {
  float y;
  asm("ex2.approx.ftz.f32 %0, %1;" : "=f"(y) : "f"(x));
  return y;
}
__device__ __forceinline__ void mma_tf32(float c[4], uint32_t a0, uint32_t a1,
                                         uint32_t a2, uint32_t a3, uint32_t b0,
                                         uint32_t b1) {
  asm volatile(
      "mma.sync.aligned.m16n8k8.row.col.f32.tf32.tf32.f32 "
      "{%0,%1,%2,%3}, {%4,%5,%6,%7}, {%8,%9}, {%0,%1,%2,%3};"
      : "+f"(c[0]), "+f"(c[1]), "+f"(c[2]), "+f"(c[3])
      : "r"(a0), "r"(a1), "r"(a2), "r"(a3), "r"(b0), "r"(b1));
}
__device__ __forceinline__ void cpa16(uint32_t* smem_dst, const void* gsrc) {
  uint32_t d = (uint32_t)__cvta_generic_to_shared(smem_dst);
  asm volatile("cp.async.cg.shared.global [%0], [%1], 16;" ::"r"(d), "l"(gsrc));
}
__device__ __forceinline__ void cp_commit() {
  asm volatile("cp.async.commit_group;");
}
__device__ __forceinline__ void cp_wait1() {
  asm volatile("cp.async.wait_group 1;");
}
__device__ __forceinline__ void cp_wait0() {
  asm volatile("cp.async.wait_group 0;");
}

// A-frag index within one [kc][rc][lane][4] tile set, RCN row-chunks tall.
__device__ __forceinline__ size_t aidx(int row, int col, int RCN) {
  int rc = row >> 4, jlo = (row >> 3) & 1, g = row & 7;
  int kc = col >> 3, t = col & 3, hi = (col >> 2) & 1;
  return ((size_t)(kc * RCN + rc) * 32 + g * 4 + t) * 4 + hi * 2 + jlo;
}
// B-frag index within one [kc][nc][lane][2] tile set, NCN col-chunks wide.
__device__ __forceinline__ size_t bidx(int n, int k, int NCN) {
  int nc = n >> 3, g = n & 7;
  int kc = k >> 3, t = k & 3, hi = (k >> 2) & 1;
  return ((size_t)(kc * NCN + nc) * 32 + g * 4 + t) * 2 + hi;
}

// ---------------------------------------------------------------------------
// Kernel 1: fused QKV projection + (extra blocks) Wp fragment conversion.
// Compute blocks [0,512): bid = (bh 32, qt 16); 128 consecutive s of ONE head
// -> epilogue stores are local to one (bh,qt) fragment tile (coalesced).
// Blocks [512,1024): convert Wp (fp32 -> tf32 B-frag layout), overlapped.
// ---------------------------------------------------------------------------
__global__ __launch_bounds__(512) void qkv_kernel(
    const float* __restrict__ x,
    const float* __restrict__ Wq, const float* __restrict__ Wk,
    const float* __restrict__ Wv, const float* __restrict__ Wp,
    const float* __restrict__ bq, const float* __restrict__ bk,
    const float* __restrict__ bv) {
  const int tid = threadIdx.x;

  if (blockIdx.x >= 512) {  // Wp conversion blocks: 2048 elems each
    int base = (blockIdx.x - 512) * 2048 + tid * 4;
    float4 w4 = *(const float4*)&Wp[base];
    int n = base >> 10, k = base & 1023;
    size_t o0 = (size_t)(n >> 7) * 131072 + (size_t)(k >> 3) * 1024;
    g_Wp[o0 + bidx(n & 127, k & 7, 16)] = f2tf(w4.x);
    g_Wp[o0 + bidx(n & 127, (k + 1) & 7, 16)] = f2tf(w4.y);
    g_Wp[o0 + bidx(n & 127, (k + 2) & 7, 16)] = f2tf(w4.z);
    g_Wp[o0 + bidx(n & 127, (k + 3) & 7, 16)] = f2tf(w4.w);
    return;
  }

  extern __shared__ uint32_t sm[];
  uint32_t* Xs = sm;               // 128*PAD
  uint32_t* Aq = Xs + 128 * PAD;   // 64*PAD each
  uint32_t* Ak = Aq + 64 * PAD;
  uint32_t* Av = Ak + 64 * PAD;
  const int qt = blockIdx.x & 15, bh = blockIdx.x >> 4;
  const int b = bh >> 4, h = bh & 15;
  const int s0 = qt * 128;

  // Weights: fp32 -> tf32 inline (L2-hot after first wave)
#pragma unroll
  for (int r = 0; r < 2; r++) {
    int f = tid + 512 * r;
    int row = f >> 4, col = (f & 15) * 4;
    float4 q4 = *(const float4*)&Wq[row * 64 + col];
    float4 k4 = *(const float4*)&Wk[row * 64 + col];
    float4 v4 = *(const float4*)&Wv[row * 64 + col];
    uint4 uq = {f2tf(q4.x), f2tf(q4.y), f2tf(q4.z), f2tf(q4.w)};
    uint4 uk = {f2tf(k4.x), f2tf(k4.y), f2tf(k4.z), f2tf(k4.w)};
    uint4 uv = {f2tf(v4.x), f2tf(v4.y), f2tf(v4.z), f2tf(v4.w)};
    *(uint4*)&Aq[row * PAD + col] = uq;
    *(uint4*)&Ak[row * PAD + col] = uk;
    *(uint4*)&Av[row * PAD + col] = uv;
  }
  // x rows for this head: global row (b*S + s0+r)*H + h, 256B contiguous each
#pragma unroll
  for (int r = 0; r < 4; r++) {
    int f = tid + 512 * r;
    int row = f >> 4, col = (f & 15) * 4;
    size_t xoff = ((size_t)((b * PS + s0 + row) * PH + h)) * 64 + col;
    float4 v = *(const float4*)&x[xoff];
    uint4 u = {f2tf(v.x), f2tf(v.y), f2tf(v.z), f2tf(v.w)};
    *(uint4*)&Xs[row * PAD + col] = u;
  }
  __syncthreads();

  const int wid = tid >> 5, lane = tid & 31;
  const int g = lane >> 2, t = lane & 3;
  const int mrow = (wid & 7) * 16;
  const int wn = wid >> 3;

  float cq[4][4] = {}, ck[4][4] = {}, cv[4][4] = {};
#pragma unroll
  for (int k0 = 0; k0 < 64; k0 += 8) {
    uint32_t a0 = Xs[(mrow + g) * PAD + k0 + t];
    uint32_t a1 = Xs[(mrow + g + 8) * PAD + k0 + t];
    uint32_t a2 = Xs[(mrow + g) * PAD + k0 + t + 4];
    uint32_t a3 = Xs[(mrow + g + 8) * PAD + k0 + t + 4];
#pragma unroll
    for (int nt = 0; nt < 4; nt++) {
      int n0 = wn * 32 + nt * 8;
      mma_tf32(cq[nt], a0, a1, a2, a3, Aq[(n0 + g) * PAD + k0 + t],
               Aq[(n0 + g) * PAD + k0 + t + 4]);
      mma_tf32(ck[nt], a0, a1, a2, a3, Ak[(n0 + g) * PAD + k0 + t],
               Ak[(n0 + g) * PAD + k0 + t + 4]);
      mma_tf32(cv[nt], a0, a1, a2, a3, Av[(n0 + g) * PAD + k0 + t],
               Av[(n0 + g) * PAD + k0 + t + 4]);
    }
  }

  const float qscale = 0.125f * 1.4426950408889634f;  // 1/sqrt(64) * log2(e)
  const size_t qbase = (size_t)(bh * 16 + qt) * 8192;
  const size_t kvbase = (size_t)(bh * 64 + qt * 4) * 2048;
#pragma unroll
  for (int nt = 0; nt < 4; nt++)
#pragma unroll
    for (int i = 0; i < 4; i++) {
      int r = mrow + g + ((i >= 2) ? 8 : 0);  // local row == s & 127
      int col = wn * 32 + nt * 8 + 2 * t + (i & 1);
      g_Q[qbase + aidx(r, col, 8)] = f2tf((cq[nt][i] + bq[col]) * qscale);
      g_K[kvbase + (size_t)(r >> 5) * 2048 + bidx(r & 31, col, 4)] =
          f2tf(ck[nt][i] + bk[col]);
      g_V[kvbase + (size_t)(r >> 5) * 2048 + bidx(col, r & 31, 8)] =
          f2tf(cv[nt][i] + bv[col]);
    }
}

// ---------------------------------------------------------------------------
// Kernel 2: causal flash attention. 256 thr. Each block processes TWO query
// tiles (qi = 15-a then a): every block = exactly 68 KV stages -> one
// balanced wave of 256 blocks. P fed to PV mma via quad shuffles (no smem).
// ---------------------------------------------------------------------------
__global__ __launch_bounds__(256) void attn_kernel() {
  extern __shared__ uint32_t sm[];
  uint32_t* Qs = sm;            // 8192: [kc 8][rc 8][lane][4]
  uint32_t* Ks = Qs + 8192;     // 2 x 2048: [kc 8][nc 4][lane][2]
  uint32_t* Vs = Ks + 4096;     // 2 x 2048: [kchunk 4][nc 8][lane][2]
  const int tid = threadIdx.x;
  const int wid = tid >> 5, lane = tid & 31;
  const int g = lane >> 2, t = lane & 3;
  const int mrow = wid * 16;
  const int bh = blockIdx.y;

  const uint32_t* Kg = g_K + (size_t)bh * 64 * 2048;
  const uint32_t* Vg = g_V + (size_t)bh * 64 * 2048;
  const int src0 = (lane & ~3) + (t >> 1);  // quad-shuffle sources for P
  const int src1 = src0 + 2;
  const bool odd = t & 1;

#pragma unroll 1
  for (int sub = 0; sub < 2; sub++) {
    const int qi = sub ? blockIdx.x : 15 - blockIdx.x;
    const int ntiles = 4 * qi + 4;
    if (sub) __syncthreads();  // all warps done with KV bufs of sub 0

    const uint32_t* Qg = g_Q + (size_t)(bh * 16 + qi) * 8192;
    // Prologue group: Q tile + KV stage 0 (contiguous copies)
#pragma unroll
    for (int r = 0; r < 8; r++) {
      int f = tid + 256 * r;
      cpa16(&Qs[f * 4], &Qg[f * 4]);
    }
#pragma unroll
    for (int r = 0; r < 2; r++) {
      int f = tid + 256 * r;
      cpa16(&Ks[f * 4], &Kg[f * 4]);
      cpa16(&Vs[f * 4], &Vg[f * 4]);
    }
    cp_commit();

    float m0 = -1e30f, m1 = -1e30f, l0 = 0.f, l1 = 0.f;
    float o[8][4] = {};
    uint32_t qf[8][4];
    const int qrow0 = qi * 128 + mrow + g;

    for (int j = 0; j < ntiles; j++) {
      const int buf = j & 1;
      if (j + 1 < ntiles) {
        const int nb = (j + 1) & 1;
        const uint32_t* Kn = Kg + (size_t)(j + 1) * 2048;
        const uint32_t* Vn = Vg + (size_t)(j + 1) * 2048;
#pragma unroll
        for (int r = 0; r < 2; r++) {
          int f = tid + 256 * r;
          cpa16(&Ks[nb * 2048 + f * 4], &Kn[f * 4]);
          cpa16(&Vs[nb * 2048 + f * 4], &Vn[f * 4]);
        }
        cp_commit();
        cp_wait1();
      } else {
        cp_wait0();
      }
      __syncthreads();  // stage j visible; all done with buf from j-1

      if (j == 0) {  // hoist Q fragments: one LDS.128 per k-chunk
#pragma unroll
        for (int kc = 0; kc < 8; kc++) {
          uint4 q4 = *(const uint4*)&Qs[((kc * 8 + wid) * 32 + lane) * 4];
          qf[kc][0] = q4.x;
          qf[kc][1] = q4.y;
          qf[kc][2] = q4.z;
          qf[kc][3] = q4.w;
        }
      }

      const uint32_t* Kb = Ks + buf * 2048;
      const uint32_t* Vb = Vs + buf * 2048;

      // S = Q @ K^T  (128 x 32 chunk)
      float s[4][4] = {};
#pragma unroll
      for (int kc = 0; kc < 8; kc++) {
#pragma unroll
        for (int nt = 0; nt < 4; nt++) {
          uint2 kb = *(const uint2*)&Kb[((kc * 4 + nt) * 32 + lane) * 2];
          mma_tf32(s[nt], qf[kc][0], qf[kc][1], qf[kc][2], qf[kc][3], kb.x,
                   kb.y);
        }
      }

      if (j >= 4 * qi) {  // only the 4 diagonal-band tiles can clip
#pragma unroll
        for (int nt = 0; nt < 4; nt++)
#pragma unroll
          for (int i = 0; i < 4; i++) {
            int col = j * 32 + nt * 8 + 2 * t + (i & 1);
            int row = qrow0 + ((i >= 2) ? 8 : 0);
            if (col > row) s[nt][i] = -1e30f;
          }
      }

      // online softmax (log2 domain), rows warp-local, quad reduce
      float rmax0 = -1e30f, rmax1 = -1e30f;
#pragma unroll
      for (int nt = 0; nt < 4; nt++) {
        rmax0 = fmaxf(rmax0, fmaxf(s[nt][0], s[nt][1]));
        rmax1 = fmaxf(rmax1, fmaxf(s[nt][2], s[nt][3]));
      }
      rmax0 = fmaxf(rmax0, __shfl_xor_sync(0xffffffffu, rmax0, 1));
      rmax0 = fmaxf(rmax0, __shfl_xor_sync(0xffffffffu, rmax0, 2));
      rmax1 = fmaxf(rmax1, __shfl_xor_sync(0xffffffffu, rmax1, 1));
      rmax1 = fmaxf(rmax1, __shfl_xor_sync(0xffffffffu, rmax1, 2));

      float nm0 = fmaxf(m0, rmax0), nm1 = fmaxf(m1, rmax1);
      float sc0 = ex2(m0 - nm0), sc1 = ex2(m1 - nm1);
      m0 = nm0;
      m1 = nm1;

      float rs0 = 0.f, rs1 = 0.f;
#pragma unroll
      for (int nt = 0; nt < 4; nt++)
#pragma unroll
        for (int i = 0; i < 4; i++) {
          float nm = (i >= 2) ? nm1 : nm0;
          float pf = __uint_as_float(f2tf(ex2(s[nt][i] - nm)));
          s[nt][i] = pf;  // tf32-rounded P, reused as mma operand via shuffle
          if (i >= 2) rs1 += pf; else rs0 += pf;
        }
      rs0 += __shfl_xor_sync(0xffffffffu, rs0, 1);
      rs0 += __shfl_xor_sync(0xffffffffu, rs0, 2);
      rs1 += __shfl_xor_sync(0xffffffffu, rs1, 1);
      rs1 += __shfl_xor_sync(0xffffffffu, rs1, 2);
      l0 = l0 * sc0 + rs0;
      l1 = l1 * sc1 + rs1;
#pragma unroll
      for (int nt = 0; nt < 8; nt++) {
        o[nt][0] *= sc0;
        o[nt][1] *= sc0;
        o[nt][2] *= sc1;
        o[nt][3] *= sc1;
      }

      // O += P @ V : P A-fragments built from s[] by quad shuffles.
      // C-frag (cols 2t,2t+1) -> A-frag (cols t,t+4): src lanes g*4+t/2 (+2).
#pragma unroll
      for (int kc = 0; kc < 4; kc++) {
        float x00 = __shfl_sync(0xffffffffu, s[kc][0], src0);
        float x01 = __shfl_sync(0xffffffffu, s[kc][1], src0);
        float x20 = __shfl_sync(0xffffffffu, s[kc][0], src1);
        float x21 = __shfl_sync(0xffffffffu, s[kc][1], src1);
        float x10 = __shfl_sync(0xffffffffu, s[kc][2], src0);
        float x11 = __shfl_sync(0xffffffffu, s[kc][3], src0);
        float x30 = __shfl_sync(0xffffffffu, s[kc][2], src1);
        float x31 = __shfl_sync(0xffffffffu, s[kc][3], src1);
        uint32_t a0 = __float_as_uint(odd ? x01 : x00);
        uint32_t a2 = __float_as_uint(odd ? x21 : x20);
        uint32_t a1 = __float_as_uint(odd ? x11 : x10);
        uint32_t a3 = __float_as_uint(odd ? x31 : x30);
#pragma unroll
        for (int nt = 0; nt < 8; nt++) {
          uint2 vb = *(const uint2*)&Vb[((kc * 8 + nt) * 32 + lane) * 2];
          mma_tf32(o[nt], a0, a1, a2, a3, vb.x, vb.y);
        }
      }
      __syncthreads();  // all warps done with buf before refill at j+1
    }

    const int b = bh >> 4, h = bh & 15;
    float inv0 = 1.f / l0, inv1 = 1.f / l1;
#pragma unroll
    for (int nt = 0; nt < 8; nt++)
#pragma unroll
      for (int i = 0; i < 4; i++) {
        int srow = qi * 128 + mrow + g + ((i >= 2) ? 8 : 0);
        int col = nt * 8 + 2 * t + (i & 1);
        int row = b * PS + srow;  // logical Y row
        int e = h * PHD + col;    // logical Y col
        size_t yi_ = (size_t)(row >> 7) * 131072 + (size_t)(e >> 3) * 1024 +
                     aidx(row & 127, e & 7, 8);
        g_Y[yi_] = f2tf(o[nt][i] * ((i >= 2) ? inv1 : inv0));
      }
  }
}

// ---------------------------------------------------------------------------
// Kernel 3: output projection. 128x128 tile/block, 256 thr, 32-deep K stages
// double-buffered. Fragment-order smem: A via LDS.128, B via LDS.64.
// ---------------------------------------------------------------------------
__global__ __launch_bounds__(256) void proj_kernel(
    const float* __restrict__ bias, float* __restrict__ out) {
  extern __shared__ uint32_t sm[];
  uint32_t* Ys = sm;            // 2 x 4096: [kc 4][rc 8][lane][4]
  uint32_t* Ws = Ys + 8192;     // 2 x 4096: [kc 4][nc 16][lane][2]
  const int tid = threadIdx.x;
  const int wid = tid >> 5, lane = tid & 31;
  const int g = lane >> 2, t = lane & 3;
  const int wm = wid & 3, wn = wid >> 2;  // 4(m) x 2(n)
  const int bm = blockIdx.y, bn = blockIdx.x;

  const uint32_t* Yg = g_Y + (size_t)bm * 131072;
  const uint32_t* Wg = g_Wp + (size_t)bn * 131072;

#pragma unroll
  for (int r = 0; r < 4; r++) {
    int f = tid + 256 * r;
    cpa16(&Ys[f * 4], &Yg[f * 4]);
    cpa16(&Ws[f * 4], &Wg[f * 4]);
  }
  cp_commit();

  float acc[2][8][4] = {};
  const int NK = PE / 32;
  for (int kt = 0; kt < NK; kt++) {
    const int buf = kt & 1;
    if (kt + 1 < NK) {
      const int nb = (kt + 1) & 1;
      const uint32_t* Yn = Yg + (size_t)(kt + 1) * 4096;
      const uint32_t* Wn = Wg + (size_t)(kt + 1) * 4096;
#pragma unroll
      for (int r = 0; r < 4; r++) {
        int f = tid + 256 * r;
        cpa16(&Ys[nb * 4096 + f * 4], &Yn[f * 4]);
        cpa16(&Ws[nb * 4096 + f * 4], &Wn[f * 4]);
      }
      cp_commit();
      cp_wait1();
    } else {
      cp_wait0();
    }
    __syncthreads();

    const uint32_t* Yb = Ys + buf * 4096;
    const uint32_t* Wb = Ws + buf * 4096;
#pragma unroll
    for (int kc = 0; kc < 4; kc++) {
      uint4 a[2];
#pragma unroll
      for (int mf = 0; mf < 2; mf++)
        a[mf] = *(const uint4*)&Yb[((kc * 8 + wm * 2 + mf) * 32 + lane) * 4];
#pragma unroll
      for (int nt = 0; nt < 8; nt++) {
        uint2 b2 = *(const uint2*)&Wb[((kc * 16 + wn * 8 + nt) * 32 + lane) * 2];
        mma_tf32(acc[0][nt], a[0].x, a[0].y, a[0].z, a[0].w, b2.x, b2.y);
        mma_tf32(acc[1][nt], a[1].x, a[1].y, a[1].z, a[1].w, b2.x, b2.y);
      }
    }
    __syncthreads();
  }

#pragma unroll
  for (int mf = 0; mf < 2; mf++)
#pragma unroll
    for (int nt = 0; nt < 8; nt++) {
      int col = bn * 128 + wn * 64 + nt * 8 + 2 * t;
      int row0 = bm * 128 + wm * 32 + mf * 16 + g;
      float2 v0 = {acc[mf][nt][0] + bias[col], acc[mf][nt][1] + bias[col + 1]};
      float2 v1 = {acc[mf][nt][2] + bias[col], acc[mf][nt][3] + bias[col + 1]};
      *(float2*)&out[(size_t)row0 * PE + col] = v0;
      *(float2*)&out[(size_t)(row0 + 8) * PE + col] = v1;
    }
}

// ---------------------------------------------------------------------------
extern "C" void kernel_launch(void* const* d_in, const int* in_sizes, int n_in,
                              void* d_out, int out_size) {
  const float* x  = (const float*)d_in[0];
  const float* Wq = (const float*)d_in[1];
  const float* bq = (const float*)d_in[2];
  const float* Wk = (const float*)d_in[3];
  const float* bk = (const float*)d_in[4];
  const float* Wv = (const float*)d_in[5];
  const float* bv = (const float*)d_in[6];
  const float* Wp = (const float*)d_in[7];
  const float* bp = (const float*)d_in[8];
  float* out = (float*)d_out;

  const int smem_qkv  = (128 + 3 * 64) * PAD * 4;        // 87,040 B
  const int smem_attn = (8192 + 4096 + 4096) * 4;        // 65,536 B
  const int smem_proj = 16384 * 4;                       // 65,536 B
  cudaFuncSetAttribute(qkv_kernel, cudaFuncAttributeMaxDynamicSharedMemorySize, smem_qkv);
  cudaFuncSetAttribute(attn_kernel, cudaFuncAttributeMaxDynamicSharedMemorySize, smem_attn);
  cudaFuncSetAttribute(proj_kernel, cudaFuncAttributeMaxDynamicSharedMemorySize, smem_proj);

  qkv_kernel<<<512 + 512, 512, smem_qkv>>>(x, Wq, Wk, Wv, Wp, bq, bk, bv);
  attn_kernel<<<dim3(8, PB * PH), 256, smem_attn>>>();
  proj_kernel<<<dim3(PE / 128, (PB * PS) / 128), 256, smem_proj>>>(bp, out);
}

// round 10
// speedup vs baseline: 2.5624x; 1.0420x over previous
#include <cuda_runtime.h>
#include <cstdint>

#define PB 2
#define PS 2048
#define PE 1024
#define PH 16
#define PHD 64
#define MROWS (PB * PS * PH)
#define PAD 68   // qkv internal tiles

// Scratch, tf32 bit patterns (allocation-free rule).
// g_Q: A-frag layout  [bh][qt 16][kc 8][rc 8][lane 32][4]
// g_K: B-frag layout  [bh][kt 64][kc 8][nc 4][lane 32][2]
// g_V: B-frag layout  [bh][vt 64][kchunk 4][nc 8][lane 32][2]
// g_Y: A-frag layout  [mt 32][kc 128][rc 8][lane 32][4]
// g_Wp: B-frag layout [nt 8][kc 128][nc 16][lane 32][2]
__device__ uint32_t g_Q[(size_t)PB * PH * PS * PHD];
__device__ uint32_t g_K[(size_t)PB * PH * PS * PHD];
__device__ uint32_t g_V[(size_t)PB * PH * PS * PHD];
__device__ uint32_t g_Y[(size_t)PB * PS * PE];
__device__ uint32_t g_Wp[(size_t)PE * PE];

__device__ __forceinline__ uint32_t f2tf(float x) {
  uint32_t u;
  asm("cvt.rna.tf32.f32 %0, %1;" : "=r"(u) : "f"(x));
  return u;
}
__device__ __forceinline__ float ex2(float x) {
  float y;
  asm("ex2.approx.ftz.f32 %0, %1;" : "=f"(y) : "f"(x));
  return y;
}
__device__ __forceinline__ void mma_tf32(float c[4], uint32_t a0, uint32_t a1,
                                         uint32_t a2, uint32_t a3, uint32_t b0,
                                         uint32_t b1) {
  asm volatile(
      "mma.sync.aligned.m16n8k8.row.col.f32.tf32.tf32.f32 "
      "{%0,%1,%2,%3}, {%4,%5,%6,%7}, {%8,%9}, {%0,%1,%2,%3};"
      : "+f"(c[0]), "+f"(c[1]), "+f"(c[2]), "+f"(c[3])
      : "r"(a0), "r"(a1), "r"(a2), "r"(a3), "r"(b0), "r"(b1));
}
__device__ __forceinline__ void cpa16(uint32_t* smem_dst, const void* gsrc) {
  uint32_t d = (uint32_t)__cvta_generic_to_shared(smem_dst);
  asm volatile("cp.async.cg.shared.global [%0], [%1], 16;" ::"r"(d), "l"(gsrc));
}
__device__ __forceinline__ void cp_commit() {
  asm volatile("cp.async.commit_group;");
}
__device__ __forceinline__ void cp_wait0() {
  asm volatile("cp.async.wait_group 0;");
}

// A-frag index within one [kc][rc][lane][4] tile set, RCN row-chunks tall.
__device__ __forceinline__ size_t aidx(int row, int col, int RCN) {
  int rc = row >> 4, jlo = (row >> 3) & 1, g = row & 7;
  int kc = col >> 3, t = col & 3, hi = (col >> 2) & 1;
  return ((size_t)(kc * RCN + rc) * 32 + g * 4 + t) * 4 + hi * 2 + jlo;
}
// B-frag index within one [kc][nc][lane][2] tile set, NCN col-chunks wide.
__device__ __forceinline__ size_t bidx(int n, int k, int NCN) {
  int nc = n >> 3, g = n & 7;
  int kc = k >> 3, t = k & 3, hi = (k >> 2) & 1;
  return ((size_t)(kc * NCN + nc) * 32 + g * 4 + t) * 2 + hi;
}

// ---------------------------------------------------------------------------
// Kernel 1: fused QKV projection + (extra blocks) Wp fragment conversion.
// Compute blocks [0,512): bid = (bh 32, qt 16); 128 consecutive s of ONE head
// -> epilogue stores are local to one (bh,qt) fragment tile (coalesced).
// Blocks [512,1024): convert Wp (fp32 -> tf32 B-frag layout), overlapped.
// ---------------------------------------------------------------------------
__global__ __launch_bounds__(512) void qkv_kernel(
    const float* __restrict__ x,
    const float* __restrict__ Wq, const float* __restrict__ Wk,
    const float* __restrict__ Wv, const float* __restrict__ Wp,
    const float* __restrict__ bq, const float* __restrict__ bk,
    const float* __restrict__ bv) {
  const int tid = threadIdx.x;

  if (blockIdx.x >= 512) {  // Wp conversion blocks: 2048 elems each
    int base = (blockIdx.x - 512) * 2048 + tid * 4;
    float4 w4 = *(const float4*)&Wp[base];
    int n = base >> 10, k = base & 1023;
    size_t o0 = (size_t)(n >> 7) * 131072 + (size_t)(k >> 3) * 1024;
    g_Wp[o0 + bidx(n & 127, k & 7, 16)] = f2tf(w4.x);
    g_Wp[o0 + bidx(n & 127, (k + 1) & 7, 16)] = f2tf(w4.y);
    g_Wp[o0 + bidx(n & 127, (k + 2) & 7, 16)] = f2tf(w4.z);
    g_Wp[o0 + bidx(n & 127, (k + 3) & 7, 16)] = f2tf(w4.w);
    return;
  }

  extern __shared__ uint32_t sm[];
  uint32_t* Xs = sm;               // 128*PAD
  uint32_t* Aq = Xs + 128 * PAD;   // 64*PAD each
  uint32_t* Ak = Aq + 64 * PAD;
  uint32_t* Av = Ak + 64 * PAD;
  const int qt = blockIdx.x & 15, bh = blockIdx.x >> 4;
  const int b = bh >> 4, h = bh & 15;
  const int s0 = qt * 128;

  // Weights: fp32 -> tf32 inline (L2-hot after first wave)
#pragma unroll
  for (int r = 0; r < 2; r++) {
    int f = tid + 512 * r;
    int row = f >> 4, col = (f & 15) * 4;
    float4 q4 = *(const float4*)&Wq[row * 64 + col];
    float4 k4 = *(const float4*)&Wk[row * 64 + col];
    float4 v4 = *(const float4*)&Wv[row * 64 + col];
    uint4 uq = {f2tf(q4.x), f2tf(q4.y), f2tf(q4.z), f2tf(q4.w)};
    uint4 uk = {f2tf(k4.x), f2tf(k4.y), f2tf(k4.z), f2tf(k4.w)};
    uint4 uv = {f2tf(v4.x), f2tf(v4.y), f2tf(v4.z), f2tf(v4.w)};
    *(uint4*)&Aq[row * PAD + col] = uq;
    *(uint4*)&Ak[row * PAD + col] = uk;
    *(uint4*)&Av[row * PAD + col] = uv;
  }
  // x rows for this head: global row (b*S + s0+r)*H + h, 256B contiguous each
#pragma unroll
  for (int r = 0; r < 4; r++) {
    int f = tid + 512 * r;
    int row = f >> 4, col = (f & 15) * 4;
    size_t xoff = ((size_t)((b * PS + s0 + row) * PH + h)) * 64 + col;
    float4 v = *(const float4*)&x[xoff];
    uint4 u = {f2tf(v.x), f2tf(v.y), f2tf(v.z), f2tf(v.w)};
    *(uint4*)&Xs[row * PAD + col] = u;
  }
  __syncthreads();

  const int wid = tid >> 5, lane = tid & 31;
  const int g = lane >> 2, t = lane & 3;
  const int mrow = (wid & 7) * 16;
  const int wn = wid >> 3;

  float cq[4][4] = {}, ck[4][4] = {}, cv[4][4] = {};
#pragma unroll
  for (int k0 = 0; k0 < 64; k0 += 8) {
    uint32_t a0 = Xs[(mrow + g) * PAD + k0 + t];
    uint32_t a1 = Xs[(mrow + g + 8) * PAD + k0 + t];
    uint32_t a2 = Xs[(mrow + g) * PAD + k0 + t + 4];
    uint32_t a3 = Xs[(mrow + g + 8) * PAD + k0 + t + 4];
#pragma unroll
    for (int nt = 0; nt < 4; nt++) {
      int n0 = wn * 32 + nt * 8;
      mma_tf32(cq[nt], a0, a1, a2, a3, Aq[(n0 + g) * PAD + k0 + t],
               Aq[(n0 + g) * PAD + k0 + t + 4]);
      mma_tf32(ck[nt], a0, a1, a2, a3, Ak[(n0 + g) * PAD + k0 + t],
               Ak[(n0 + g) * PAD + k0 + t + 4]);
      mma_tf32(cv[nt], a0, a1, a2, a3, Av[(n0 + g) * PAD + k0 + t],
               Av[(n0 + g) * PAD + k0 + t + 4]);
    }
  }

  const float qscale = 0.125f * 1.4426950408889634f;  // 1/sqrt(64) * log2(e)
  const size_t qbase = (size_t)(bh * 16 + qt) * 8192;
  const size_t kvbase = (size_t)(bh * 64 + qt * 4) * 2048;
#pragma unroll
  for (int nt = 0; nt < 4; nt++)
#pragma unroll
    for (int i = 0; i < 4; i++) {
      int r = mrow + g + ((i >= 2) ? 8 : 0);  // local row == s & 127
      int col = wn * 32 + nt * 8 + 2 * t + (i & 1);
      g_Q[qbase + aidx(r, col, 8)] = f2tf((cq[nt][i] + bq[col]) * qscale);
      g_K[kvbase + (size_t)(r >> 5) * 2048 + bidx(r & 31, col, 4)] =
          f2tf(ck[nt][i] + bk[col]);
      g_V[kvbase + (size_t)(r >> 5) * 2048 + bidx(col, r & 31, 8)] =
          f2tf(cv[nt][i] + bv[col]);
    }
}

// ---------------------------------------------------------------------------
// Kernel 2: causal flash attention. 256 thr. Each block processes TWO query
// tiles (qi = 15-a then a): every block = exactly 68 KV stages -> one
// balanced wave of 256 blocks. ONE barrier per stage (prefetch-after-barrier
// into the slot freed two stages ago). Softmax ex2/shuffles interleaved with
// PV MMAs per k-chunk so MUFU hides behind the tensor pipe.
// ---------------------------------------------------------------------------
__global__ __launch_bounds__(256) void attn_kernel() {
  extern __shared__ uint32_t sm[];
  uint32_t* Qs = sm;            // 8192: [kc 8][rc 8][lane][4]
  uint32_t* Ks = Qs + 8192;     // 2 x 2048: [kc 8][nc 4][lane][2]
  uint32_t* Vs = Ks + 4096;     // 2 x 2048: [kchunk 4][nc 8][lane][2]
  const int tid = threadIdx.x;
  const int wid = tid >> 5, lane = tid & 31;
  const int g = lane >> 2, t = lane & 3;
  const int mrow = wid * 16;
  const int bh = blockIdx.y;

  const uint32_t* Kg = g_K + (size_t)bh * 64 * 2048;
  const uint32_t* Vg = g_V + (size_t)bh * 64 * 2048;
  const int src0 = (lane & ~3) + (t >> 1);  // quad-shuffle sources for P
  const int src1 = src0 + 2;
  const bool odd = t & 1;

#pragma unroll 1
  for (int sub = 0; sub < 2; sub++) {
    const int qi = sub ? blockIdx.x : 15 - blockIdx.x;
    const int ntiles = 4 * qi + 4;

    const uint32_t* Qg = g_Q + (size_t)(bh * 16 + qi) * 8192;
    // Prologue group: Q tile + KV stage 0 into buf 0.
    // (Safe at sub=1: Qs was only read at sub=0's j==0 hoist; KV buf 0 was
    //  last read at stage ntiles-2, retired by the barrier at stage ntiles-1.)
#pragma unroll
    for (int r = 0; r < 8; r++) {
      int f = tid + 256 * r;
      cpa16(&Qs[f * 4], &Qg[f * 4]);
    }
#pragma unroll
    for (int r = 0; r < 2; r++) {
      int f = tid + 256 * r;
      cpa16(&Ks[f * 4], &Kg[f * 4]);
      cpa16(&Vs[f * 4], &Vg[f * 4]);
    }
    cp_commit();

    float m0 = -1e30f, m1 = -1e30f, l0 = 0.f, l1 = 0.f;
    float o[8][4] = {};
    uint32_t qf[8][4];
    const int qrow0 = qi * 128 + mrow + g;

    for (int j = 0; j < ntiles; j++) {
      cp_wait0();       // own copies for stage j arrived
      __syncthreads();  // stage j visible to all; all warps done with j-1

      // Prefetch stage j+1 into buf (j+1)&1 (freed at j-1, retired by the
      // barrier above). Overlaps with compute of stage j.
      if (j + 1 < ntiles) {
        const int nb = (j + 1) & 1;
        const uint32_t* Kn = Kg + (size_t)(j + 1) * 2048;
        const uint32_t* Vn = Vg + (size_t)(j + 1) * 2048;
#pragma unroll
        for (int r = 0; r < 2; r++) {
          int f = tid + 256 * r;
          cpa16(&Ks[nb * 2048 + f * 4], &Kn[f * 4]);
          cpa16(&Vs[nb * 2048 + f * 4], &Vn[f * 4]);
        }
        cp_commit();
      }

      if (j == 0) {  // hoist Q fragments: one LDS.128 per k-chunk
#pragma unroll
        for (int kc = 0; kc < 8; kc++) {
          uint4 q4 = *(const uint4*)&Qs[((kc * 8 + wid) * 32 + lane) * 4];
          qf[kc][0] = q4.x;
          qf[kc][1] = q4.y;
          qf[kc][2] = q4.z;
          qf[kc][3] = q4.w;
        }
      }

      const uint32_t* Kb = Ks + (j & 1) * 2048;
      const uint32_t* Vb = Vs + (j & 1) * 2048;

      // S = Q @ K^T  (128 x 32 chunk)
      float s[4][4] = {};
#pragma unroll
      for (int kc = 0; kc < 8; kc++) {
#pragma unroll
        for (int nt = 0; nt < 4; nt++) {
          uint2 kb = *(const uint2*)&Kb[((kc * 4 + nt) * 32 + lane) * 2];
          mma_tf32(s[nt], qf[kc][0], qf[kc][1], qf[kc][2], qf[kc][3], kb.x,
                   kb.y);
        }
      }

      if (j >= 4 * qi) {  // only the 4 diagonal-band tiles can clip
#pragma unroll
        for (int nt = 0; nt < 4; nt++)
#pragma unroll
          for (int i = 0; i < 4; i++) {
            int col = j * 32 + nt * 8 + 2 * t + (i & 1);
            int row = qrow0 + ((i >= 2) ? 8 : 0);
            if (col > row) s[nt][i] = -1e30f;
          }
      }

      // online softmax (log2 domain), rows warp-local, quad reduce
      float rmax0 = -1e30f, rmax1 = -1e30f;
#pragma unroll
      for (int nt = 0; nt < 4; nt++) {
        rmax0 = fmaxf(rmax0, fmaxf(s[nt][0], s[nt][1]));
        rmax1 = fmaxf(rmax1, fmaxf(s[nt][2], s[nt][3]));
      }
      rmax0 = fmaxf(rmax0, __shfl_xor_sync(0xffffffffu, rmax0, 1));
      rmax0 = fmaxf(rmax0, __shfl_xor_sync(0xffffffffu, rmax0, 2));
      rmax1 = fmaxf(rmax1, __shfl_xor_sync(0xffffffffu, rmax1, 1));
      rmax1 = fmaxf(rmax1, __shfl_xor_sync(0xffffffffu, rmax1, 2));

      float nm0 = fmaxf(m0, rmax0), nm1 = fmaxf(m1, rmax1);
      float sc0 = ex2(m0 - nm0), sc1 = ex2(m1 - nm1);
      m0 = nm0;
      m1 = nm1;
#pragma unroll
      for (int nt = 0; nt < 8; nt++) {
        o[nt][0] *= sc0;
        o[nt][1] *= sc0;
        o[nt][2] *= sc1;
        o[nt][3] *= sc1;
      }

      // Interleaved: per k-chunk, build P (ex2 + quad shuffles) then feed its
      // 8 PV MMAs. ex2 of chunk kc+1 overlaps the tensor pipe on chunk kc.
      float rs0 = 0.f, rs1 = 0.f;
#pragma unroll
      for (int kc = 0; kc < 4; kc++) {
        float p0 = __uint_as_float(f2tf(ex2(s[kc][0] - nm0)));
        float p1 = __uint_as_float(f2tf(ex2(s[kc][1] - nm0)));
        float p2 = __uint_as_float(f2tf(ex2(s[kc][2] - nm1)));
        float p3 = __uint_as_float(f2tf(ex2(s[kc][3] - nm1)));
        rs0 += p0;
        rs0 += p1;
        rs1 += p2;
        rs1 += p3;
        // C-frag (cols 2t,2t+1) -> A-frag (cols t,t+4): src lanes g*4+t/2(+2)
        float x00 = __shfl_sync(0xffffffffu, p0, src0);
        float x01 = __shfl_sync(0xffffffffu, p1, src0);
        float x20 = __shfl_sync(0xffffffffu, p0, src1);
        float x21 = __shfl_sync(0xffffffffu, p1, src1);
        float x10 = __shfl_sync(0xffffffffu, p2, src0);
        float x11 = __shfl_sync(0xffffffffu, p3, src0);
        float x30 = __shfl_sync(0xffffffffu, p2, src1);
        float x31 = __shfl_sync(0xffffffffu, p3, src1);
        uint32_t a0 = __float_as_uint(odd ? x01 : x00);
        uint32_t a2 = __float_as_uint(odd ? x21 : x20);
        uint32_t a1 = __float_as_uint(odd ? x11 : x10);
        uint32_t a3 = __float_as_uint(odd ? x31 : x30);
#pragma unroll
        for (int nt = 0; nt < 8; nt++) {
          uint2 vb = *(const uint2*)&Vb[((kc * 8 + nt) * 32 + lane) * 2];
          mma_tf32(o[nt], a0, a1, a2, a3, vb.x, vb.y);
        }
      }
      rs0 += __shfl_xor_sync(0xffffffffu, rs0, 1);
      rs0 += __shfl_xor_sync(0xffffffffu, rs0, 2);
      rs1 += __shfl_xor_sync(0xffffffffu, rs1, 1);
      rs1 += __shfl_xor_sync(0xffffffffu, rs1, 2);
      l0 = l0 * sc0 + rs0;
      l1 = l1 * sc1 + rs1;
    }

    const int b = bh >> 4, h = bh & 15;
    float inv0 = 1.f / l0, inv1 = 1.f / l1;
#pragma unroll
    for (int nt = 0; nt < 8; nt++)
#pragma unroll
      for (int i = 0; i < 4; i++) {
        int srow = qi * 128 + mrow + g + ((i >= 2) ? 8 : 0);
        int col = nt * 8 + 2 * t + (i & 1);
        int row = b * PS + srow;  // logical Y row
        int e = h * PHD + col;    // logical Y col
        size_t yi_ = (size_t)(row >> 7) * 131072 + (size_t)(e >> 3) * 1024 +
                     aidx(row & 127, e & 7, 8);
        g_Y[yi_] = f2tf(o[nt][i] * ((i >= 2) ? inv1 : inv0));
      }
  }
}

// ---------------------------------------------------------------------------
// Kernel 3: output projection. 128x128 tile/block, 256 thr, 32-deep K stages
// double-buffered, ONE barrier per stage. A via LDS.128, B via LDS.64.
// ---------------------------------------------------------------------------
__global__ __launch_bounds__(256) void proj_kernel(
    const float* __restrict__ bias, float* __restrict__ out) {
  extern __shared__ uint32_t sm[];
  uint32_t* Ys = sm;            // 2 x 4096: [kc 4][rc 8][lane][4]
  uint32_t* Ws = Ys + 8192;     // 2 x 4096: [kc 4][nc 16][lane][2]
  const int tid = threadIdx.x;
  const int wid = tid >> 5, lane = tid & 31;
  const int g = lane >> 2, t = lane & 3;
  const int wm = wid & 3, wn = wid >> 2;  // 4(m) x 2(n)
  const int bm = blockIdx.y, bn = blockIdx.x;

  const uint32_t* Yg = g_Y + (size_t)bm * 131072;
  const uint32_t* Wg = g_Wp + (size_t)bn * 131072;

#pragma unroll
  for (int r = 0; r < 4; r++) {
    int f = tid + 256 * r;
    cpa16(&Ys[f * 4], &Yg[f * 4]);
    cpa16(&Ws[f * 4], &Wg[f * 4]);
  }
  cp_commit();

  float acc[2][8][4] = {};
  const int NK = PE / 32;
  for (int kt = 0; kt < NK; kt++) {
    cp_wait0();
    __syncthreads();  // stage kt visible; all warps done with kt-1

    if (kt + 1 < NK) {  // prefetch into slot freed at kt-1
      const int nb = (kt + 1) & 1;
      const uint32_t* Yn = Yg + (size_t)(kt + 1) * 4096;
      const uint32_t* Wn = Wg + (size_t)(kt + 1) * 4096;
#pragma unroll
      for (int r = 0; r < 4; r++) {
        int f = tid + 256 * r;
        cpa16(&Ys[nb * 4096 + f * 4], &Yn[f * 4]);
        cpa16(&Ws[nb * 4096 + f * 4], &Wn[f * 4]);
      }
      cp_commit();
    }

    const uint32_t* Yb = Ys + (kt & 1) * 4096;
    const uint32_t* Wb = Ws + (kt & 1) * 4096;
#pragma unroll
    for (int kc = 0; kc < 4; kc++) {
      uint4 a[2];
#pragma unroll
      for (int mf = 0; mf < 2; mf++)
        a[mf] = *(const uint4*)&Yb[((kc * 8 + wm * 2 + mf) * 32 + lane) * 4];
#pragma unroll
      for (int nt = 0; nt < 8; nt++) {
        uint2 b2 = *(const uint2*)&Wb[((kc * 16 + wn * 8 + nt) * 32 + lane) * 2];
        mma_tf32(acc[0][nt], a[0].x, a[0].y, a[0].z, a[0].w, b2.x, b2.y);
        mma_tf32(acc[1][nt], a[1].x, a[1].y, a[1].z, a[1].w, b2.x, b2.y);
      }
    }
  }

#pragma unroll
  for (int mf = 0; mf < 2; mf++)
#pragma unroll
    for (int nt = 0; nt < 8; nt++) {
      int col = bn * 128 + wn * 64 + nt * 8 + 2 * t;
      int row0 = bm * 128 + wm * 32 + mf * 16 + g;
      float2 v0 = {acc[mf][nt][0] + bias[col], acc[mf][nt][1] + bias[col + 1]};
      float2 v1 = {acc[mf][nt][2] + bias[col], acc[mf][nt][3] + bias[col + 1]};
      *(float2*)&out[(size_t)row0 * PE + col] = v0;
      *(float2*)&out[(size_t)(row0 + 8) * PE + col] = v1;
    }
}

// ---------------------------------------------------------------------------
extern "C" void kernel_launch(void* const* d_in, const int* in_sizes, int n_in,
                              void* d_out, int out_size) {
  const float* x  = (const float*)d_in[0];
  const float* Wq = (const float*)d_in[1];
  const float* bq = (const float*)d_in[2];
  const float* Wk = (const float*)d_in[3];
  const float* bk = (const float*)d_in[4];
  const float* Wv = (const float*)d_in[5];
  const float* bv = (const float*)d_in[6];
  const float* Wp = (const float*)d_in[7];
  const float* bp = (const float*)d_in[8];
  float* out = (float*)d_out;

  const int smem_qkv  = (128 + 3 * 64) * PAD * 4;        // 87,040 B
  const int smem_attn = (8192 + 4096 + 4096) * 4;        // 65,536 B
  const int smem_proj = 16384 * 4;                       // 65,536 B
  cudaFuncSetAttribute(qkv_kernel, cudaFuncAttributeMaxDynamicSharedMemorySize, smem_qkv);
  cudaFuncSetAttribute(attn_kernel, cudaFuncAttributeMaxDynamicSharedMemorySize, smem_attn);
  cudaFuncSetAttribute(proj_kernel, cudaFuncAttributeMaxDynamicSharedMemorySize, smem_proj);

  qkv_kernel<<<512 + 512, 512, smem_qkv>>>(x, Wq, Wk, Wv, Wp, bq, bk, bv);
  attn_kernel<<<dim3(8, PB * PH), 256, smem_attn>>>();
  proj_kernel<<<dim3(PE / 128, (PB * PS) / 128), 256, smem_proj>>>(bp, out);
}

// round 11
// speedup vs baseline: 2.6129x; 1.0197x over previous
#include <cuda_runtime.h>
#include <cstdint>

#define PB 2
#define PS 2048
#define PE 1024
#define PH 16
#define PHD 64
#define MROWS (PB * PS * PH)
#define PAD 68   // qkv internal tiles

// Scratch, tf32 bit patterns (allocation-free rule).
// g_Q: A-frag layout  [bh][qt 16][kc 8][rc 8][lane 32][4]
// g_K: B-frag layout  [bh][kt 64][kc 8][nc 4][lane 32][2]
// g_V: B-frag layout  [bh][vt 64][kchunk 4][nc 8][lane 32][2]
// g_Y: A-frag layout  [mt 32][kc 128][rc 8][lane 32][4]
// g_Wp: B-frag layout [nt 8][kc 128][nc 16][lane 32][2]
__device__ uint32_t g_Q[(size_t)PB * PH * PS * PHD];
__device__ uint32_t g_K[(size_t)PB * PH * PS * PHD];
__device__ uint32_t g_V[(size_t)PB * PH * PS * PHD];
__device__ uint32_t g_Y[(size_t)PB * PS * PE];
__device__ uint32_t g_Wp[(size_t)PE * PE];

__device__ __forceinline__ uint32_t f2tf(float x) {
  uint32_t u;
  asm("cvt.rna.tf32.f32 %0, %1;" : "=r"(u) : "f"(x));
  return u;
}
__device__ __forceinline__ float ex2(float x) {
  float y;
  asm("ex2.approx.ftz.f32 %0, %1;" : "=f"(y) : "f"(x));
  return y;
}
__device__ __forceinline__ void mma_tf32(float c[4], uint32_t a0, uint32_t a1,
                                         uint32_t a2, uint32_t a3, uint32_t b0,
                                         uint32_t b1) {
  asm volatile(
      "mma.sync.aligned.m16n8k8.row.col.f32.tf32.tf32.f32 "
      "{%0,%1,%2,%3}, {%4,%5,%6,%7}, {%8,%9}, {%0,%1,%2,%3};"
      : "+f"(c[0]), "+f"(c[1]), "+f"(c[2]), "+f"(c[3])
      : "r"(a0), "r"(a1), "r"(a2), "r"(a3), "r"(b0), "r"(b1));
}
__device__ __forceinline__ void cpa16(uint32_t* smem_dst, const void* gsrc) {
  uint32_t d = (uint32_t)__cvta_generic_to_shared(smem_dst);
  asm volatile("cp.async.cg.shared.global [%0], [%1], 16;" ::"r"(d), "l"(gsrc));
}
__device__ __forceinline__ void cp_commit() {
  asm volatile("cp.async.commit_group;");
}
__device__ __forceinline__ void cp_wait0() {
  asm volatile("cp.async.wait_group 0;");
}

// A-frag index within one [kc][rc][lane][4] tile set, RCN row-chunks tall.
__device__ __forceinline__ size_t aidx(int row, int col, int RCN) {
  int rc = row >> 4, jlo = (row >> 3) & 1, g = row & 7;
  int kc = col >> 3, t = col & 3, hi = (col >> 2) & 1;
  return ((size_t)(kc * RCN + rc) * 32 + g * 4 + t) * 4 + hi * 2 + jlo;
}
// B-frag index within one [kc][nc][lane][2] tile set, NCN col-chunks wide.
__device__ __forceinline__ size_t bidx(int n, int k, int NCN) {
  int nc = n >> 3, g = n & 7;
  int kc = k >> 3, t = k & 3, hi = (k >> 2) & 1;
  return ((size_t)(kc * NCN + nc) * 32 + g * 4 + t) * 2 + hi;
}

// ---------------------------------------------------------------------------
// Kernel 1: fused QKV projection + (extra blocks) Wp fragment conversion.
// Compute blocks [0,512): bid = (bh 32, qt 16); 128 consecutive s of ONE head.
// Blocks [512,1024): convert Wp (fp32 -> tf32 B-frag layout), overlapped.
// ---------------------------------------------------------------------------
__global__ __launch_bounds__(512) void qkv_kernel(
    const float* __restrict__ x,
    const float* __restrict__ Wq, const float* __restrict__ Wk,
    const float* __restrict__ Wv, const float* __restrict__ Wp,
    const float* __restrict__ bq, const float* __restrict__ bk,
    const float* __restrict__ bv) {
  const int tid = threadIdx.x;

  if (blockIdx.x >= 512) {  // Wp conversion blocks: 2048 elems each
    int base = (blockIdx.x - 512) * 2048 + tid * 4;
    float4 w4 = *(const float4*)&Wp[base];
    int n = base >> 10, k = base & 1023;
    size_t o0 = (size_t)(n >> 7) * 131072 + (size_t)(k >> 3) * 1024;
    g_Wp[o0 + bidx(n & 127, k & 7, 16)] = f2tf(w4.x);
    g_Wp[o0 + bidx(n & 127, (k + 1) & 7, 16)] = f2tf(w4.y);
    g_Wp[o0 + bidx(n & 127, (k + 2) & 7, 16)] = f2tf(w4.z);
    g_Wp[o0 + bidx(n & 127, (k + 3) & 7, 16)] = f2tf(w4.w);
    return;
  }

  extern __shared__ uint32_t sm[];
  uint32_t* Xs = sm;               // 128*PAD
  uint32_t* Aq = Xs + 128 * PAD;   // 64*PAD each
  uint32_t* Ak = Aq + 64 * PAD;
  uint32_t* Av = Ak + 64 * PAD;
  const int qt = blockIdx.x & 15, bh = blockIdx.x >> 4;
  const int b = bh >> 4, h = bh & 15;
  const int s0 = qt * 128;

  // Weights: fp32 -> tf32 inline (L2-hot after first wave)
#pragma unroll
  for (int r = 0; r < 2; r++) {
    int f = tid + 512 * r;
    int row = f >> 4, col = (f & 15) * 4;
    float4 q4 = *(const float4*)&Wq[row * 64 + col];
    float4 k4 = *(const float4*)&Wk[row * 64 + col];
    float4 v4 = *(const float4*)&Wv[row * 64 + col];
    uint4 uq = {f2tf(q4.x), f2tf(q4.y), f2tf(q4.z), f2tf(q4.w)};
    uint4 uk = {f2tf(k4.x), f2tf(k4.y), f2tf(k4.z), f2tf(k4.w)};
    uint4 uv = {f2tf(v4.x), f2tf(v4.y), f2tf(v4.z), f2tf(v4.w)};
    *(uint4*)&Aq[row * PAD + col] = uq;
    *(uint4*)&Ak[row * PAD + col] = uk;
    *(uint4*)&Av[row * PAD + col] = uv;
  }
  // x rows for this head: global row (b*S + s0+r)*H + h, 256B contiguous each
#pragma unroll
  for (int r = 0; r < 4; r++) {
    int f = tid + 512 * r;
    int row = f >> 4, col = (f & 15) * 4;
    size_t xoff = ((size_t)((b * PS + s0 + row) * PH + h)) * 64 + col;
    float4 v = *(const float4*)&x[xoff];
    uint4 u = {f2tf(v.x), f2tf(v.y), f2tf(v.z), f2tf(v.w)};
    *(uint4*)&Xs[row * PAD + col] = u;
  }
  __syncthreads();

  const int wid = tid >> 5, lane = tid & 31;
  const int g = lane >> 2, t = lane & 3;
  const int mrow = (wid & 7) * 16;
  const int wn = wid >> 3;

  float cq[4][4] = {}, ck[4][4] = {}, cv[4][4] = {};
#pragma unroll
  for (int k0 = 0; k0 < 64; k0 += 8) {
    uint32_t a0 = Xs[(mrow + g) * PAD + k0 + t];
    uint32_t a1 = Xs[(mrow + g + 8) * PAD + k0 + t];
    uint32_t a2 = Xs[(mrow + g) * PAD + k0 + t + 4];
    uint32_t a3 = Xs[(mrow + g + 8) * PAD + k0 + t + 4];
#pragma unroll
    for (int nt = 0; nt < 4; nt++) {
      int n0 = wn * 32 + nt * 8;
      mma_tf32(cq[nt], a0, a1, a2, a3, Aq[(n0 + g) * PAD + k0 + t],
               Aq[(n0 + g) * PAD + k0 + t + 4]);
      mma_tf32(ck[nt], a0, a1, a2, a3, Ak[(n0 + g) * PAD + k0 + t],
               Ak[(n0 + g) * PAD + k0 + t + 4]);
      mma_tf32(cv[nt], a0, a1, a2, a3, Av[(n0 + g) * PAD + k0 + t],
               Av[(n0 + g) * PAD + k0 + t + 4]);
    }
  }

  const float qscale = 0.125f * 1.4426950408889634f;  // 1/sqrt(64) * log2(e)
  const size_t qbase = (size_t)(bh * 16 + qt) * 8192;
  const size_t kvbase = (size_t)(bh * 64 + qt * 4) * 2048;
#pragma unroll
  for (int nt = 0; nt < 4; nt++)
#pragma unroll
    for (int i = 0; i < 4; i++) {
      int r = mrow + g + ((i >= 2) ? 8 : 0);  // local row == s & 127
      int col = wn * 32 + nt * 8 + 2 * t + (i & 1);
      g_Q[qbase + aidx(r, col, 8)] = f2tf((cq[nt][i] + bq[col]) * qscale);
      g_K[kvbase + (size_t)(r >> 5) * 2048 + bidx(r & 31, col, 4)] =
          f2tf(ck[nt][i] + bk[col]);
      g_V[kvbase + (size_t)(r >> 5) * 2048 + bidx(col, r & 31, 8)] =
          f2tf(cv[nt][i] + bv[col]);
    }
}

// ---------------------------------------------------------------------------
// Kernel 2: causal flash attention. 256 thr, forced 2 blocks/SM. BN=64 KV
// stages (halves softmax bookkeeping per MMA and barrier count). Each block
// runs two query tiles (qi = 15-a then a) -> exactly 36 stages/block, one
// balanced wave of 256 blocks. One barrier per stage; P via quad shuffles.
// ---------------------------------------------------------------------------
__global__ __launch_bounds__(256, 2) void attn_kernel() {
  extern __shared__ uint32_t sm[];
  uint32_t* Qs = sm;            // 8192: [kc 8][rc 8][lane][4]
  uint32_t* Ks = Qs + 8192;     // 2 bufs x 4096 (64 rows, two kt tiles)
  uint32_t* Vs = Ks + 8192;     // 2 bufs x 4096
  const int tid = threadIdx.x;
  const int wid = tid >> 5, lane = tid & 31;
  const int g = lane >> 2, t = lane & 3;
  const int mrow = wid * 16;
  const int bh = blockIdx.y;

  const uint32_t* Kg = g_K + (size_t)bh * 64 * 2048;
  const uint32_t* Vg = g_V + (size_t)bh * 64 * 2048;
  const int src0 = (lane & ~3) + (t >> 1);  // quad-shuffle sources for P
  const int src1 = src0 + 2;
  const bool odd = t & 1;

#pragma unroll 1
  for (int sub = 0; sub < 2; sub++) {
    const int qi = sub ? blockIdx.x : 15 - blockIdx.x;
    const int ntiles = 2 * qi + 2;  // 64-row stages
    if (sub) __syncthreads();       // Qs/bufs of sub 0 fully consumed

    const uint32_t* Qg = g_Q + (size_t)(bh * 16 + qi) * 8192;
    // Prologue group: Q tile + KV stage 0 into buf 0 (contiguous copies)
#pragma unroll
    for (int r = 0; r < 8; r++) {
      int f = tid + 256 * r;
      cpa16(&Qs[f * 4], &Qg[f * 4]);
    }
#pragma unroll
    for (int r = 0; r < 4; r++) {
      int f = tid + 256 * r;
      cpa16(&Ks[f * 4], &Kg[f * 4]);
      cpa16(&Vs[f * 4], &Vg[f * 4]);
    }
    cp_commit();

    float m0 = -1e30f, m1 = -1e30f, l0 = 0.f, l1 = 0.f;
    float o[8][4] = {};
    const int qrow0 = qi * 128 + mrow + g;

    for (int j = 0; j < ntiles; j++) {
      cp_wait0();       // copies for stage j arrived
      __syncthreads();  // stage j visible to all; all warps done with j-1

      // Prefetch stage j+1 into buf (j+1)&1 (freed at j-1, retired above).
      if (j + 1 < ntiles) {
        const int nb = (j + 1) & 1;
        const uint32_t* Kn = Kg + (size_t)(j + 1) * 4096;
        const uint32_t* Vn = Vg + (size_t)(j + 1) * 4096;
#pragma unroll
        for (int r = 0; r < 4; r++) {
          int f = tid + 256 * r;
          cpa16(&Ks[nb * 4096 + f * 4], &Kn[f * 4]);
          cpa16(&Vs[nb * 4096 + f * 4], &Vn[f * 4]);
        }
        cp_commit();
      }

      const uint32_t* Kb = Ks + (j & 1) * 4096;
      const uint32_t* Vb = Vs + (j & 1) * 4096;

      // S = Q @ K^T  (128 x 64 chunk). Q frags re-read per stage (LDS.128).
      float s[8][4] = {};
#pragma unroll
      for (int kc = 0; kc < 8; kc++) {
        uint4 q4 = *(const uint4*)&Qs[((kc * 8 + wid) * 32 + lane) * 4];
#pragma unroll
        for (int n = 0; n < 8; n++) {
          // K stage: two kt tiles; tile (n>>2), nc (n&3) within it
          uint2 kb = *(const uint2*)&Kb[((n >> 2) * 2048 +
                                         ((kc * 4 + (n & 3)) * 32 + lane) * 2)];
          mma_tf32(s[n], q4.x, q4.y, q4.z, q4.w, kb.x, kb.y);
        }
      }

      if (j >= 2 * qi) {  // only the last two stages can clip
#pragma unroll
        for (int n = 0; n < 8; n++)
#pragma unroll
          for (int i = 0; i < 4; i++) {
            int col = j * 64 + n * 8 + 2 * t + (i & 1);
            int row = qrow0 + ((i >= 2) ? 8 : 0);
            if (col > row) s[n][i] = -1e30f;
          }
      }

      // online softmax (log2 domain), rows warp-local, quad reduce
      float rmax0 = -1e30f, rmax1 = -1e30f;
#pragma unroll
      for (int n = 0; n < 8; n++) {
        rmax0 = fmaxf(rmax0, fmaxf(s[n][0], s[n][1]));
        rmax1 = fmaxf(rmax1, fmaxf(s[n][2], s[n][3]));
      }
      rmax0 = fmaxf(rmax0, __shfl_xor_sync(0xffffffffu, rmax0, 1));
      rmax0 = fmaxf(rmax0, __shfl_xor_sync(0xffffffffu, rmax0, 2));
      rmax1 = fmaxf(rmax1, __shfl_xor_sync(0xffffffffu, rmax1, 1));
      rmax1 = fmaxf(rmax1, __shfl_xor_sync(0xffffffffu, rmax1, 2));

      float nm0 = fmaxf(m0, rmax0), nm1 = fmaxf(m1, rmax1);
      float sc0 = ex2(m0 - nm0), sc1 = ex2(m1 - nm1);
      m0 = nm0;
      m1 = nm1;
#pragma unroll
      for (int n = 0; n < 8; n++) {
        o[n][0] *= sc0;
        o[n][1] *= sc0;
        o[n][2] *= sc1;
        o[n][3] *= sc1;
      }

      // Interleaved: per k-chunk, build P (ex2 + quad shuffles) then its 8 PV
      // MMAs; ex2 of chunk kc+1 overlaps the tensor pipe on chunk kc.
      float rs0 = 0.f, rs1 = 0.f;
#pragma unroll
      for (int kc = 0; kc < 8; kc++) {
        float p0 = __uint_as_float(f2tf(ex2(s[kc][0] - nm0)));
        float p1 = __uint_as_float(f2tf(ex2(s[kc][1] - nm0)));
        float p2 = __uint_as_float(f2tf(ex2(s[kc][2] - nm1)));
        float p3 = __uint_as_float(f2tf(ex2(s[kc][3] - nm1)));
        rs0 += p0;
        rs0 += p1;
        rs1 += p2;
        rs1 += p3;
        // C-frag (cols 2t,2t+1) -> A-frag (cols t,t+4): src lanes g*4+t/2(+2)
        float x00 = __shfl_sync(0xffffffffu, p0, src0);
        float x01 = __shfl_sync(0xffffffffu, p1, src0);
        float x20 = __shfl_sync(0xffffffffu, p0, src1);
        float x21 = __shfl_sync(0xffffffffu, p1, src1);
        float x10 = __shfl_sync(0xffffffffu, p2, src0);
        float x11 = __shfl_sync(0xffffffffu, p3, src0);
        float x30 = __shfl_sync(0xffffffffu, p2, src1);
        float x31 = __shfl_sync(0xffffffffu, p3, src1);
        uint32_t a0 = __float_as_uint(odd ? x01 : x00);
        uint32_t a2 = __float_as_uint(odd ? x21 : x20);
        uint32_t a1 = __float_as_uint(odd ? x11 : x10);
        uint32_t a3 = __float_as_uint(odd ? x31 : x30);
        // V stage: [vt 2][kc 4][nc 8] -> contiguous in kchunk kc (stride 512)
#pragma unroll
        for (int nt = 0; nt < 8; nt++) {
          uint2 vb = *(const uint2*)&Vb[((kc * 8 + nt) * 32 + lane) * 2];
          mma_tf32(o[nt], a0, a1, a2, a3, vb.x, vb.y);
        }
      }
      rs0 += __shfl_xor_sync(0xffffffffu, rs0, 1);
      rs0 += __shfl_xor_sync(0xffffffffu, rs0, 2);
      rs1 += __shfl_xor_sync(0xffffffffu, rs1, 1);
      rs1 += __shfl_xor_sync(0xffffffffu, rs1, 2);
      l0 = l0 * sc0 + rs0;
      l1 = l1 * sc1 + rs1;
    }

    const int b = bh >> 4, h = bh & 15;
    float inv0 = 1.f / l0, inv1 = 1.f / l1;
#pragma unroll
    for (int nt = 0; nt < 8; nt++)
#pragma unroll
      for (int i = 0; i < 4; i++) {
        int srow = qi * 128 + mrow + g + ((i >= 2) ? 8 : 0);
        int col = nt * 8 + 2 * t + (i & 1);
        int row = b * PS + srow;  // logical Y row
        int e = h * PHD + col;    // logical Y col
        size_t yi_ = (size_t)(row >> 7) * 131072 + (size_t)(e >> 3) * 1024 +
                     aidx(row & 127, e & 7, 8);
        g_Y[yi_] = f2tf(o[nt][i] * ((i >= 2) ? inv1 : inv0));
      }
  }
}

// ---------------------------------------------------------------------------
// Kernel 3: output projection. 128x128 tile/block, 256 thr, 32-deep K stages
// double-buffered, ONE barrier per stage. A via LDS.128, B via LDS.64.
// ---------------------------------------------------------------------------
__global__ __launch_bounds__(256) void proj_kernel(
    const float* __restrict__ bias, float* __restrict__ out) {
  extern __shared__ uint32_t sm[];
  uint32_t* Ys = sm;            // 2 x 4096: [kc 4][rc 8][lane][4]
  uint32_t* Ws = Ys + 8192;     // 2 x 4096: [kc 4][nc 16][lane][2]
  const int tid = threadIdx.x;
  const int wid = tid >> 5, lane = tid & 31;
  const int g = lane >> 2, t = lane & 3;
  const int wm = wid & 3, wn = wid >> 2;  // 4(m) x 2(n)
  const int bm = blockIdx.y, bn = blockIdx.x;

  const uint32_t* Yg = g_Y + (size_t)bm * 131072;
  const uint32_t* Wg = g_Wp + (size_t)bn * 131072;

#pragma unroll
  for (int r = 0; r < 4; r++) {
    int f = tid + 256 * r;
    cpa16(&Ys[f * 4], &Yg[f * 4]);
    cpa16(&Ws[f * 4], &Wg[f * 4]);
  }
  cp_commit();

  float acc[2][8][4] = {};
  const int NK = PE / 32;
  for (int kt = 0; kt < NK; kt++) {
    cp_wait0();
    __syncthreads();  // stage kt visible; all warps done with kt-1

    if (kt + 1 < NK) {  // prefetch into slot freed at kt-1
      const int nb = (kt + 1) & 1;
      const uint32_t* Yn = Yg + (size_t)(kt + 1) * 4096;
      const uint32_t* Wn = Wg + (size_t)(kt + 1) * 4096;
#pragma unroll
      for (int r = 0; r < 4; r++) {
        int f = tid + 256 * r;
        cpa16(&Ys[nb * 4096 + f * 4], &Yn[f * 4]);
        cpa16(&Ws[nb * 4096 + f * 4], &Wn[f * 4]);
      }
      cp_commit();
    }

    const uint32_t* Yb = Ys + (kt & 1) * 4096;
    const uint32_t* Wb = Ws + (kt & 1) * 4096;
#pragma unroll
    for (int kc = 0; kc < 4; kc++) {
      uint4 a[2];
#pragma unroll
      for (int mf = 0; mf < 2; mf++)
        a[mf] = *(const uint4*)&Yb[((kc * 8 + wm * 2 + mf) * 32 + lane) * 4];
#pragma unroll
      for (int nt = 0; nt < 8; nt++) {
        uint2 b2 = *(const uint2*)&Wb[((kc * 16 + wn * 8 + nt) * 32 + lane) * 2];
        mma_tf32(acc[0][nt], a[0].x, a[0].y, a[0].z, a[0].w, b2.x, b2.y);
        mma_tf32(acc[1][nt], a[1].x, a[1].y, a[1].z, a[1].w, b2.x, b2.y);
      }
    }
  }

#pragma unroll
  for (int mf = 0; mf < 2; mf++)
#pragma unroll
    for (int nt = 0; nt < 8; nt++) {
      int col = bn * 128 + wn * 64 + nt * 8 + 2 * t;
      int row0 = bm * 128 + wm * 32 + mf * 16 + g;
      float2 v0 = {acc[mf][nt][0] + bias[col], acc[mf][nt][1] + bias[col + 1]};
      float2 v1 = {acc[mf][nt][2] + bias[col], acc[mf][nt][3] + bias[col + 1]};
      *(float2*)&out[(size_t)row0 * PE + col] = v0;
      *(float2*)&out[(size_t)(row0 + 8) * PE + col] = v1;
    }
}

// ---------------------------------------------------------------------------
extern "C" void kernel_launch(void* const* d_in, const int* in_sizes, int n_in,
                              void* d_out, int out_size) {
  const float* x  = (const float*)d_in[0];
  const float* Wq = (const float*)d_in[1];
  const float* bq = (const float*)d_in[2];
  const float* Wk = (const float*)d_in[3];
  const float* bk = (const float*)d_in[4];
  const float* Wv = (const float*)d_in[5];
  const float* bv = (const float*)d_in[6];
  const float* Wp = (const float*)d_in[7];
  const float* bp = (const float*)d_in[8];
  float* out = (float*)d_out;

  const int smem_qkv  = (128 + 3 * 64) * PAD * 4;        // 87,040 B
  const int smem_attn = (8192 + 8192 + 8192) * 4;        // 98,304 B
  const int smem_proj = 16384 * 4;                       // 65,536 B
  cudaFuncSetAttribute(qkv_kernel, cudaFuncAttributeMaxDynamicSharedMemorySize, smem_qkv);
  cudaFuncSetAttribute(attn_kernel, cudaFuncAttributeMaxDynamicSharedMemorySize, smem_attn);
  cudaFuncSetAttribute(proj_kernel, cudaFuncAttributeMaxDynamicSharedMemorySize, smem_proj);

  qkv_kernel<<<512 + 512, 512, smem_qkv>>>(x, Wq, Wk, Wv, Wp, bq, bk, bv);
  attn_kernel<<<dim3(8, PB * PH), 256, smem_attn>>>();
  proj_kernel<<<dim3(PE / 128, (PB * PS) / 128), 256, smem_proj>>>(bp, out);
}

// round 12
// speedup vs baseline: 2.6919x; 1.0302x over previous
#include <cuda_runtime.h>
#include <cstdint>

#define PB 2
#define PS 2048
#define PE 1024
#define PH 16
#define PHD 64
#define MROWS (PB * PS * PH)
#define PAD 68   // qkv internal tiles

// Scratch, tf32 bit patterns (allocation-free rule).
// g_Q: A-frag layout  [bh][qt 16][kc 8][rc 8][lane 32][4]
// g_K: B-frag layout  [bh][kt 64][kc 8][nc 4][lane 32][2]
// g_V: B-frag layout  [bh][vt 64][kchunk 4][nc 8][lane 32][2]
// g_Y: A-frag layout  [mt 32][kc 128][rc 8][lane 32][4]
// g_Wp: B-frag layout [nt 8][kc 128][nc 16][lane 32][2]
__device__ uint32_t g_Q[(size_t)PB * PH * PS * PHD];
__device__ uint32_t g_K[(size_t)PB * PH * PS * PHD];
__device__ uint32_t g_V[(size_t)PB * PH * PS * PHD];
__device__ uint32_t g_Y[(size_t)PB * PS * PE];
__device__ uint32_t g_Wp[(size_t)PE * PE];

__device__ __forceinline__ uint32_t f2tf(float x) {
  uint32_t u;
  asm("cvt.rna.tf32.f32 %0, %1;" : "=r"(u) : "f"(x));
  return u;
}
__device__ __forceinline__ float ex2(float x) {
  float y;
  asm("ex2.approx.ftz.f32 %0, %1;" : "=f"(y) : "f"(x));
  return y;
}
__device__ __forceinline__ void mma_tf32(float c[4], uint32_t a0, uint32_t a1,
                                         uint32_t a2, uint32_t a3, uint32_t b0,
                                         uint32_t b1) {
  asm volatile(
      "mma.sync.aligned.m16n8k8.row.col.f32.tf32.tf32.f32 "
      "{%0,%1,%2,%3}, {%4,%5,%6,%7}, {%8,%9}, {%0,%1,%2,%3};"
      : "+f"(c[0]), "+f"(c[1]), "+f"(c[2]), "+f"(c[3])
      : "r"(a0), "r"(a1), "r"(a2), "r"(a3), "r"(b0), "r"(b1));
}
__device__ __forceinline__ void cpa16(uint32_t* smem_dst, const void* gsrc) {
  uint32_t d = (uint32_t)__cvta_generic_to_shared(smem_dst);
  asm volatile("cp.async.cg.shared.global [%0], [%1], 16;" ::"r"(d), "l"(gsrc));
}
__device__ __forceinline__ void cp_commit() {
  asm volatile("cp.async.commit_group;");
}
__device__ __forceinline__ void cp_wait0() {
  asm volatile("cp.async.wait_group 0;");
}

// A-frag index within one [kc][rc][lane][4] tile set, RCN row-chunks tall.
__device__ __forceinline__ size_t aidx(int row, int col, int RCN) {
  int rc = row >> 4, jlo = (row >> 3) & 1, g = row & 7;
  int kc = col >> 3, t = col & 3, hi = (col >> 2) & 1;
  return ((size_t)(kc * RCN + rc) * 32 + g * 4 + t) * 4 + hi * 2 + jlo;
}

// ---------------------------------------------------------------------------
// Kernel 1: fused QKV projection + (extra blocks) Wp fragment conversion.
// Compute blocks [0,512): bid = (bh 32, qt 16); 128 consecutive s of ONE head.
// Epilogue converts C-frags to A/B-frag register order via quad/cross-quad
// shuffles -> Q stored as STG.128, K/V as STG.64, all warp-contiguous.
// Blocks [512,768): convert Wp, 8 k per thread -> 2 contiguous STG.128.
// ---------------------------------------------------------------------------
__global__ __launch_bounds__(512) void qkv_kernel(
    const float* __restrict__ x,
    const float* __restrict__ Wq, const float* __restrict__ Wk,
    const float* __restrict__ Wv, const float* __restrict__ Wp,
    const float* __restrict__ bq, const float* __restrict__ bk,
    const float* __restrict__ bv) {
  const int tid = threadIdx.x;

  if (blockIdx.x >= 512) {  // Wp conversion: one n, 8 k per thread
    int p = (blockIdx.x - 512) * 512 + tid;  // 0..131071
    int n = p & 1023, kg = p >> 10;          // kg = k-chunk (8 wide)
    const float* src = &Wp[(size_t)n * 1024 + kg * 8];
    float4 w0 = *(const float4*)src;
    float4 w1 = *(const float4*)(src + 4);
    // word j = t'*2+hi holds k = kg*8 + hi*4 + t'
    uint4 ua = {f2tf(w0.x), f2tf(w1.x), f2tf(w0.y), f2tf(w1.y)};
    uint4 ub = {f2tf(w0.z), f2tf(w1.z), f2tf(w0.w), f2tf(w1.w)};
    size_t o = (size_t)(n >> 7) * 131072 + (size_t)kg * 1024 +
               ((n >> 3) & 15) * 64 + (n & 7) * 8;
    *(uint4*)&g_Wp[o] = ua;
    *(uint4*)&g_Wp[o + 4] = ub;
    return;
  }

  extern __shared__ uint32_t sm[];
  uint32_t* Xs = sm;               // 128*PAD
  uint32_t* Aq = Xs + 128 * PAD;   // 64*PAD each
  uint32_t* Ak = Aq + 64 * PAD;
  uint32_t* Av = Ak + 64 * PAD;
  const int qt = blockIdx.x & 15, bh = blockIdx.x >> 4;
  const int b = bh >> 4, h = bh & 15;
  const int s0 = qt * 128;

  // Weights: fp32 -> tf32 inline (L2-hot after first wave)
#pragma unroll
  for (int r = 0; r < 2; r++) {
    int f = tid + 512 * r;
    int row = f >> 4, col = (f & 15) * 4;
    float4 q4 = *(const float4*)&Wq[row * 64 + col];
    float4 k4 = *(const float4*)&Wk[row * 64 + col];
    float4 v4 = *(const float4*)&Wv[row * 64 + col];
    uint4 uq = {f2tf(q4.x), f2tf(q4.y), f2tf(q4.z), f2tf(q4.w)};
    uint4 uk = {f2tf(k4.x), f2tf(k4.y), f2tf(k4.z), f2tf(k4.w)};
    uint4 uv = {f2tf(v4.x), f2tf(v4.y), f2tf(v4.z), f2tf(v4.w)};
    *(uint4*)&Aq[row * PAD + col] = uq;
    *(uint4*)&Ak[row * PAD + col] = uk;
    *(uint4*)&Av[row * PAD + col] = uv;
  }
  // x rows for this head: global row (b*S + s0+r)*H + h, 256B contiguous each
#pragma unroll
  for (int r = 0; r < 4; r++) {
    int f = tid + 512 * r;
    int row = f >> 4, col = (f & 15) * 4;
    size_t xoff = ((size_t)((b * PS + s0 + row) * PH + h)) * 64 + col;
    float4 v = *(const float4*)&x[xoff];
    uint4 u = {f2tf(v.x), f2tf(v.y), f2tf(v.z), f2tf(v.w)};
    *(uint4*)&Xs[row * PAD + col] = u;
  }
  __syncthreads();

  const int wid = tid >> 5, lane = tid & 31;
  const int g = lane >> 2, t = lane & 3;
  const int mrow = (wid & 7) * 16;
  const int wn = wid >> 3;

  float cq[4][4] = {}, ck[4][4] = {}, cv[4][4] = {};
#pragma unroll
  for (int k0 = 0; k0 < 64; k0 += 8) {
    uint32_t a0 = Xs[(mrow + g) * PAD + k0 + t];
    uint32_t a1 = Xs[(mrow + g + 8) * PAD + k0 + t];
    uint32_t a2 = Xs[(mrow + g) * PAD + k0 + t + 4];
    uint32_t a3 = Xs[(mrow + g + 8) * PAD + k0 + t + 4];
#pragma unroll
    for (int nt = 0; nt < 4; nt++) {
      int n0 = wn * 32 + nt * 8;
      mma_tf32(cq[nt], a0, a1, a2, a3, Aq[(n0 + g) * PAD + k0 + t],
               Aq[(n0 + g) * PAD + k0 + t + 4]);
      mma_tf32(ck[nt], a0, a1, a2, a3, Ak[(n0 + g) * PAD + k0 + t],
               Ak[(n0 + g) * PAD + k0 + t + 4]);
      mma_tf32(cv[nt], a0, a1, a2, a3, Av[(n0 + g) * PAD + k0 + t],
               Av[(n0 + g) * PAD + k0 + t + 4]);
    }
  }

  const float qscale = 0.125f * 1.4426950408889634f;  // 1/sqrt(64) * log2(e)
  const size_t qbase = (size_t)(bh * 16 + qt) * 8192;
  const size_t kvb = (size_t)(bh * 64 + qt * 4) * 2048 +
                     (size_t)(mrow >> 5) * 2048;  // this warp's 32-row kt tile
  const int rc = wid & 7;
  const int nc0 = (mrow & 31) >> 3;  // 0 or 2: row-group within kt tile
  const int src0 = (lane & ~3) + (t >> 1), src1 = src0 + 2;
  const bool odd = t & 1;
  const int srcV0 = (lane & 3) * 4 + (lane >> 3);  // V cross-quad sources
  const int srcV1 = srcV0 + 16;
  const bool selv = (lane >> 2) & 1;

#pragma unroll
  for (int nt = 0; nt < 4; nt++) {
    const int kcol = wn * 4 + nt;  // k-chunk of cols kcol*8..+7
    uint32_t vq[4], vk[4], vv[4];
#pragma unroll
    for (int i = 0; i < 4; i++) {
      int col = kcol * 8 + 2 * t + (i & 1);
      vq[i] = f2tf((cq[nt][i] + bq[col]) * qscale);
      vk[i] = f2tf(ck[nt][i] + bk[col]);
      vv[i] = f2tf(cv[nt][i] + bv[col]);
    }
    // Q: C-frag -> A-frag via quad shuffles, one STG.128
    {
      uint32_t x00 = __shfl_sync(~0u, vq[0], src0);
      uint32_t x01 = __shfl_sync(~0u, vq[1], src0);
      uint32_t x10 = __shfl_sync(~0u, vq[2], src0);
      uint32_t x11 = __shfl_sync(~0u, vq[3], src0);
      uint32_t x20 = __shfl_sync(~0u, vq[0], src1);
      uint32_t x21 = __shfl_sync(~0u, vq[1], src1);
      uint32_t x30 = __shfl_sync(~0u, vq[2], src1);
      uint32_t x31 = __shfl_sync(~0u, vq[3], src1);
      uint4 u = {odd ? x01 : x00, odd ? x11 : x10, odd ? x21 : x20,
                 odd ? x31 : x30};
      *(uint4*)&g_Q[qbase + ((size_t)(kcol * 8 + rc) * 32 + lane) * 4] = u;
    }
    // K: same shuffle pattern -> two STG.64 (rows g -> nc0, rows g+8 -> nc0+1)
    {
      uint32_t x00 = __shfl_sync(~0u, vk[0], src0);
      uint32_t x01 = __shfl_sync(~0u, vk[1], src0);
      uint32_t x10 = __shfl_sync(~0u, vk[2], src0);
      uint32_t x11 = __shfl_sync(~0u, vk[3], src0);
      uint32_t x20 = __shfl_sync(~0u, vk[0], src1);
      uint32_t x21 = __shfl_sync(~0u, vk[1], src1);
      uint32_t x30 = __shfl_sync(~0u, vk[2], src1);
      uint32_t x31 = __shfl_sync(~0u, vk[3], src1);
      uint2 u0 = {odd ? x01 : x00, odd ? x21 : x20};  // row g: k=t, k=t+4
      uint2 u1 = {odd ? x11 : x10, odd ? x31 : x30};  // row g+8
      *(uint2*)&g_K[kvb + ((size_t)(kcol * 4 + nc0) * 32 + lane) * 2] = u0;
      *(uint2*)&g_K[kvb + ((size_t)(kcol * 4 + nc0 + 1) * 32 + lane) * 2] = u1;
    }
    // V: transpose remap (dest lane d: gd=d>>2 is col&7, td=d&3 is k&3)
    {
      uint32_t y00 = __shfl_sync(~0u, vv[0], srcV0);
      uint32_t y01 = __shfl_sync(~0u, vv[1], srcV0);
      uint32_t y10 = __shfl_sync(~0u, vv[0], srcV1);
      uint32_t y11 = __shfl_sync(~0u, vv[1], srcV1);
      uint2 u0 = {selv ? y01 : y00, selv ? y11 : y10};  // rows block h=0
      uint32_t z00 = __shfl_sync(~0u, vv[2], srcV0);
      uint32_t z01 = __shfl_sync(~0u, vv[3], srcV0);
      uint32_t z10 = __shfl_sync(~0u, vv[2], srcV1);
      uint32_t z11 = __shfl_sync(~0u, vv[3], srcV1);
      uint2 u1 = {selv ? z01 : z00, selv ? z11 : z10};  // rows block h=1
      *(uint2*)&g_V[kvb + ((size_t)(nc0 * 8 + kcol) * 32 + lane) * 2] = u0;
      *(uint2*)&g_V[kvb + ((size_t)((nc0 + 1) * 8 + kcol) * 32 + lane) * 2] = u1;
    }
  }
}

// ---------------------------------------------------------------------------
// Kernel 2: causal flash attention. 256 thr, forced 2 blocks/SM. BN=64 KV
// stages. Each block runs two query tiles (qi = 15-a then a) -> 36 stages,
// one balanced wave of 256 blocks. One barrier per stage; P via quad shuffles.
// ---------------------------------------------------------------------------
__global__ __launch_bounds__(256, 2) void attn_kernel() {
  extern __shared__ uint32_t sm[];
  uint32_t* Qs = sm;            // 8192: [kc 8][rc 8][lane][4]
  uint32_t* Ks = Qs + 8192;     // 2 bufs x 4096 (64 rows, two kt tiles)
  uint32_t* Vs = Ks + 8192;     // 2 bufs x 4096
  const int tid = threadIdx.x;
  const int wid = tid >> 5, lane = tid & 31;
  const int g = lane >> 2, t = lane & 3;
  const int mrow = wid * 16;
  const int bh = blockIdx.y;

  const uint32_t* Kg = g_K + (size_t)bh * 64 * 2048;
  const uint32_t* Vg = g_V + (size_t)bh * 64 * 2048;
  const int src0 = (lane & ~3) + (t >> 1);  // quad-shuffle sources for P
  const int src1 = src0 + 2;
  const bool odd = t & 1;

#pragma unroll 1
  for (int sub = 0; sub < 2; sub++) {
    const int qi = sub ? blockIdx.x : 15 - blockIdx.x;
    const int ntiles = 2 * qi + 2;  // 64-row stages
    if (sub) __syncthreads();       // Qs/bufs of sub 0 fully consumed

    const uint32_t* Qg = g_Q + (size_t)(bh * 16 + qi) * 8192;
    // Prologue group: Q tile + KV stage 0 into buf 0 (contiguous copies)
#pragma unroll
    for (int r = 0; r < 8; r++) {
      int f = tid + 256 * r;
      cpa16(&Qs[f * 4], &Qg[f * 4]);
    }
#pragma unroll
    for (int r = 0; r < 4; r++) {
      int f = tid + 256 * r;
      cpa16(&Ks[f * 4], &Kg[f * 4]);
      cpa16(&Vs[f * 4], &Vg[f * 4]);
    }
    cp_commit();

    float m0 = -1e30f, m1 = -1e30f, l0 = 0.f, l1 = 0.f;
    float o[8][4] = {};
    const int qrow0 = qi * 128 + mrow + g;

    for (int j = 0; j < ntiles; j++) {
      cp_wait0();       // copies for stage j arrived
      __syncthreads();  // stage j visible to all; all warps done with j-1

      // Prefetch stage j+1 into buf (j+1)&1 (freed at j-1, retired above).
      if (j + 1 < ntiles) {
        const int nb = (j + 1) & 1;
        const uint32_t* Kn = Kg + (size_t)(j + 1) * 4096;
        const uint32_t* Vn = Vg + (size_t)(j + 1) * 4096;
#pragma unroll
        for (int r = 0; r < 4; r++) {
          int f = tid + 256 * r;
          cpa16(&Ks[nb * 4096 + f * 4], &Kn[f * 4]);
          cpa16(&Vs[nb * 4096 + f * 4], &Vn[f * 4]);
        }
        cp_commit();
      }

      const uint32_t* Kb = Ks + (j & 1) * 4096;
      const uint32_t* Vb = Vs + (j & 1) * 4096;

      // S = Q @ K^T  (128 x 64 chunk). Q frags re-read per stage (LDS.128).
      float s[8][4] = {};
#pragma unroll
      for (int kc = 0; kc < 8; kc++) {
        uint4 q4 = *(const uint4*)&Qs[((kc * 8 + wid) * 32 + lane) * 4];
#pragma unroll
        for (int n = 0; n < 8; n++) {
          uint2 kb = *(const uint2*)&Kb[((n >> 2) * 2048 +
                                         ((kc * 4 + (n & 3)) * 32 + lane) * 2)];
          mma_tf32(s[n], q4.x, q4.y, q4.z, q4.w, kb.x, kb.y);
        }
      }

      if (j >= 2 * qi) {  // only the last two stages can clip
#pragma unroll
        for (int n = 0; n < 8; n++)
#pragma unroll
          for (int i = 0; i < 4; i++) {
            int col = j * 64 + n * 8 + 2 * t + (i & 1);
            int row = qrow0 + ((i >= 2) ? 8 : 0);
            if (col > row) s[n][i] = -1e30f;
          }
      }

      // online softmax (log2 domain), rows warp-local, quad reduce
      float rmax0 = -1e30f, rmax1 = -1e30f;
#pragma unroll
      for (int n = 0; n < 8; n++) {
        rmax0 = fmaxf(rmax0, fmaxf(s[n][0], s[n][1]));
        rmax1 = fmaxf(rmax1, fmaxf(s[n][2], s[n][3]));
      }
      rmax0 = fmaxf(rmax0, __shfl_xor_sync(0xffffffffu, rmax0, 1));
      rmax0 = fmaxf(rmax0, __shfl_xor_sync(0xffffffffu, rmax0, 2));
      rmax1 = fmaxf(rmax1, __shfl_xor_sync(0xffffffffu, rmax1, 1));
      rmax1 = fmaxf(rmax1, __shfl_xor_sync(0xffffffffu, rmax1, 2));

      float nm0 = fmaxf(m0, rmax0), nm1 = fmaxf(m1, rmax1);
      float sc0 = ex2(m0 - nm0), sc1 = ex2(m1 - nm1);
      m0 = nm0;
      m1 = nm1;
#pragma unroll
      for (int n = 0; n < 8; n++) {
        o[n][0] *= sc0;
        o[n][1] *= sc0;
        o[n][2] *= sc1;
        o[n][3] *= sc1;
      }

      // Interleaved: per k-chunk, build P (ex2 + quad shuffles) then its 8 PV
      // MMAs; ex2 of chunk kc+1 overlaps the tensor pipe on chunk kc.
      float rs0 = 0.f, rs1 = 0.f;
#pragma unroll
      for (int kc = 0; kc < 8; kc++) {
        float p0 = __uint_as_float(f2tf(ex2(s[kc][0] - nm0)));
        float p1 = __uint_as_float(f2tf(ex2(s[kc][1] - nm0)));
        float p2 = __uint_as_float(f2tf(ex2(s[kc][2] - nm1)));
        float p3 = __uint_as_float(f2tf(ex2(s[kc][3] - nm1)));
        rs0 += p0;
        rs0 += p1;
        rs1 += p2;
        rs1 += p3;
        float x00 = __shfl_sync(0xffffffffu, p0, src0);
        float x01 = __shfl_sync(0xffffffffu, p1, src0);
        float x20 = __shfl_sync(0xffffffffu, p0, src1);
        float x21 = __shfl_sync(0xffffffffu, p1, src1);
        float x10 = __shfl_sync(0xffffffffu, p2, src0);
        float x11 = __shfl_sync(0xffffffffu, p3, src0);
        float x30 = __shfl_sync(0xffffffffu, p2, src1);
        float x31 = __shfl_sync(0xffffffffu, p3, src1);
        uint32_t a0 = __float_as_uint(odd ? x01 : x00);
        uint32_t a2 = __float_as_uint(odd ? x21 : x20);
        uint32_t a1 = __float_as_uint(odd ? x11 : x10);
        uint32_t a3 = __float_as_uint(odd ? x31 : x30);
#pragma unroll
        for (int nt = 0; nt < 8; nt++) {
          uint2 vb = *(const uint2*)&Vb[((kc * 8 + nt) * 32 + lane) * 2];
          mma_tf32(o[nt], a0, a1, a2, a3, vb.x, vb.y);
        }
      }
      rs0 += __shfl_xor_sync(0xffffffffu, rs0, 1);
      rs0 += __shfl_xor_sync(0xffffffffu, rs0, 2);
      rs1 += __shfl_xor_sync(0xffffffffu, rs1, 1);
      rs1 += __shfl_xor_sync(0xffffffffu, rs1, 2);
      l0 = l0 * sc0 + rs0;
      l1 = l1 * sc1 + rs1;
    }

    const int b = bh >> 4, h = bh & 15;
    float inv0 = 1.f / l0, inv1 = 1.f / l1;
#pragma unroll
    for (int nt = 0; nt < 8; nt++)
#pragma unroll
      for (int i = 0; i < 4; i++) {
        int srow = qi * 128 + mrow + g + ((i >= 2) ? 8 : 0);
        int col = nt * 8 + 2 * t + (i & 1);
        int row = b * PS + srow;  // logical Y row
        int e = h * PHD + col;    // logical Y col
        size_t yi_ = (size_t)(row >> 7) * 131072 + (size_t)(e >> 3) * 1024 +
                     aidx(row & 127, e & 7, 8);
        g_Y[yi_] = f2tf(o[nt][i] * ((i >= 2) ? inv1 : inv0));
      }
  }
}

// ---------------------------------------------------------------------------
// Kernel 3: output projection. 128x128 tile/block, 256 thr, 32-deep K stages
// double-buffered, ONE barrier per stage. A via LDS.128, B via LDS.64.
// ---------------------------------------------------------------------------
__global__ __launch_bounds__(256) void proj_kernel(
    const float* __restrict__ bias, float* __restrict__ out) {
  extern __shared__ uint32_t sm[];
  uint32_t* Ys = sm;            // 2 x 4096: [kc 4][rc 8][lane][4]
  uint32_t* Ws = Ys + 8192;     // 2 x 4096: [kc 4][nc 16][lane][2]
  const int tid = threadIdx.x;
  const int wid = tid >> 5, lane = tid & 31;
  const int g = lane >> 2, t = lane & 3;
  const int wm = wid & 3, wn = wid >> 2;  // 4(m) x 2(n)
  const int bm = blockIdx.y, bn = blockIdx.x;

  const uint32_t* Yg = g_Y + (size_t)bm * 131072;
  const uint32_t* Wg = g_Wp + (size_t)bn * 131072;

#pragma unroll
  for (int r = 0; r < 4; r++) {
    int f = tid + 256 * r;
    cpa16(&Ys[f * 4], &Yg[f * 4]);
    cpa16(&Ws[f * 4], &Wg[f * 4]);
  }
  cp_commit();

  float acc[2][8][4] = {};
  const int NK = PE / 32;
  for (int kt = 0; kt < NK; kt++) {
    cp_wait0();
    __syncthreads();  // stage kt visible; all warps done with kt-1

    if (kt + 1 < NK) {  // prefetch into slot freed at kt-1
      const int nb = (kt + 1) & 1;
      const uint32_t* Yn = Yg + (size_t)(kt + 1) * 4096;
      const uint32_t* Wn = Wg + (size_t)(kt + 1) * 4096;
#pragma unroll
      for (int r = 0; r < 4; r++) {
        int f = tid + 256 * r;
        cpa16(&Ys[nb * 4096 + f * 4], &Yn[f * 4]);
        cpa16(&Ws[nb * 4096 + f * 4], &Wn[f * 4]);
      }
      cp_commit();
    }

    const uint32_t* Yb = Ys + (kt & 1) * 4096;
    const uint32_t* Wb = Ws + (kt & 1) * 4096;
#pragma unroll
    for (int kc = 0; kc < 4; kc++) {
      uint4 a[2];
#pragma unroll
      for (int mf = 0; mf < 2; mf++)
        a[mf] = *(const uint4*)&Yb[((kc * 8 + wm * 2 + mf) * 32 + lane) * 4];
#pragma unroll
      for (int nt = 0; nt < 8; nt++) {
        uint2 b2 = *(const uint2*)&Wb[((kc * 16 + wn * 8 + nt) * 32 + lane) * 2];
        mma_tf32(acc[0][nt], a[0].x, a[0].y, a[0].z, a[0].w, b2.x, b2.y);
        mma_tf32(acc[1][nt], a[1].x, a[1].y, a[1].z, a[1].w, b2.x, b2.y);
      }
    }
  }

#pragma unroll
  for (int mf = 0; mf < 2; mf++)
#pragma unroll
    for (int nt = 0; nt < 8; nt++) {
      int col = bn * 128 + wn * 64 + nt * 8 + 2 * t;
      int row0 = bm * 128 + wm * 32 + mf * 16 + g;
      float2 v0 = {acc[mf][nt][0] + bias[col], acc[mf][nt][1] + bias[col + 1]};
      float2 v1 = {acc[mf][nt][2] + bias[col], acc[mf][nt][3] + bias[col + 1]};
      *(float2*)&out[(size_t)row0 * PE + col] = v0;
      *(float2*)&out[(size_t)(row0 + 8) * PE + col] = v1;
    }
}

// ---------------------------------------------------------------------------
extern "C" void kernel_launch(void* const* d_in, const int* in_sizes, int n_in,
                              void* d_out, int out_size) {
  const float* x  = (const float*)d_in[0];
  const float* Wq = (const float*)d_in[1];
  const float* bq = (const float*)d_in[2];
  const float* Wk = (const float*)d_in[3];
  const float* bk = (const float*)d_in[4];
  const float* Wv = (const float*)d_in[5];
  const float* bv = (const float*)d_in[6];
  const float* Wp = (const float*)d_in[7];
  const float* bp = (const float*)d_in[8];
  float* out = (float*)d_out;

  const int smem_qkv  = (128 + 3 * 64) * PAD * 4;        // 87,040 B
  const int smem_attn = (8192 + 8192 + 8192) * 4;        // 98,304 B
  const int smem_proj = 16384 * 4;                       // 65,536 B
  cudaFuncSetAttribute(qkv_kernel, cudaFuncAttributeMaxDynamicSharedMemorySize, smem_qkv);
  cudaFuncSetAttribute(attn_kernel, cudaFuncAttributeMaxDynamicSharedMemorySize, smem_attn);
  cudaFuncSetAttribute(proj_kernel, cudaFuncAttributeMaxDynamicSharedMemorySize, smem_proj);

  qkv_kernel<<<512 + 256, 512, smem_qkv>>>(x, Wq, Wk, Wv, Wp, bq, bk, bv);
  attn_kernel<<<dim3(8, PB * PH), 256, smem_attn>>>();
  proj_kernel<<<dim3(PE / 128, (PB * PS) / 128), 256, smem_proj>>>(bp, out);
}